// round 7
// baseline (speedup 1.0000x reference)
#include <cuda_runtime.h>
#include <cstdint>
#include <math.h>

#define DIM   8192
#define BATCH 8
#define TOPK  60
#define NENT  (BATCH * TOPK)   // 480 merged sparse entries

typedef unsigned long long ull;
typedef unsigned int uint;

// ---------------- device scratch (no allocations allowed) ----------------
__device__ float g_act[BATCH * DIM];               // step-1 sigmoid output
__device__ float g_z2 [BATCH * DIM];               // step-2 sigmoid output
__device__ ull   g_sdr_paired[(BATCH / 2) * DIM];  // sdr packed as (b,b+1) f32 pairs
__device__ float g_vals[BATCH * 64];               // top-k values, idx-sorted per batch
__device__ int   g_idxs[BATCH * 64];               // top-k indices, ascending per batch
__device__ int   g_skey[NENT];                     // merged entries: (col<<3)|b, ascending
__device__ float g_sval[NENT];                     // merged entry values

// ---------------- helpers ----------------
__device__ __forceinline__ float sigmoidf(float x) {
    return 1.0f / (1.0f + expf(-x));   // precise expf: selection must match reference
}
__device__ __forceinline__ ull pack2(float x, float y) {
    ull r; asm("mov.b64 %0, {%1,%2};" : "=l"(r) : "f"(x), "f"(y)); return r;
}
__device__ __forceinline__ void unpack2(ull v, float &x, float &y) {
    asm("mov.b64 {%0,%1}, %2;" : "=f"(x), "=f"(y) : "l"(v));
}
__device__ __forceinline__ void fma2(ull &d, ull a, ull b) {
    asm("fma.rn.f32x2 %0, %1, %2, %0;" : "+l"(d) : "l"(a), "l"(b));
}

// ---------------- kernel 0: pack sdr into batch-pairs ----------------
__global__ void pair_sdr_kernel(const float* __restrict__ sdr) {
    int k = blockIdx.x * blockDim.x + threadIdx.x;
    if (k < DIM) {
#pragma unroll
        for (int p = 0; p < BATCH / 2; p++) {
            g_sdr_paired[p * DIM + k] =
                pack2(sdr[(2 * p) * DIM + k], sdr[(2 * p + 1) * DIM + k]);
        }
    }
}

// ---------------- kernel 1: dense GEMV-8 + sigmoid ----------------
// Warp owns 8 consecutive rows j (amortizes sdr L1 traffic over 2x rows vs R6);
// lane sweeps k in float4 units; explicit syn double-buffer keeps ~32 lines
// in flight per warp. Block = 128 threads (4 warps), grid = 256.
__global__ __launch_bounds__(128, 2) void gemv_dense_kernel(const float* __restrict__ syn) {
    int warp = blockIdx.x * 4 + (threadIdx.x >> 5);   // 1024 warps
    int lane = threadIdx.x & 31;
    int j0 = warp * 8;

    const float4* r[8];
#pragma unroll
    for (int i = 0; i < 8; i++)
        r[i] = (const float4*)(syn + (size_t)(j0 + i) * DIM);

    ull acc[8][4];
#pragma unroll
    for (int i = 0; i < 8; i++)
#pragma unroll
        for (int p = 0; p < 4; p++) acc[i][p] = 0ull;

    float4 cur[8], nxt[8];
#pragma unroll
    for (int i = 0; i < 8; i++) cur[i] = r[i][lane];

    for (int it = 0; it < 64; it++) {                 // 64 iterations of 4 k per lane
        int k4 = (it + 1) * 32 + lane;
        if (it < 63) {
#pragma unroll
            for (int i = 0; i < 8; i++) nxt[i] = r[i][k4];
        }
        int k = (it * 32 + lane) * 4;
        ulonglong2 sA[4], sB[4];                      // sA[p]=(k,k+1), sB[p]=(k+2,k+3)
#pragma unroll
        for (int p = 0; p < 4; p++) {
            const ulonglong2* sp = (const ulonglong2*)&g_sdr_paired[p * DIM + k];
            sA[p] = sp[0];
            sB[p] = sp[1];
        }
#pragma unroll
        for (int i = 0; i < 8; i++) {
            float4 a = cur[i];
            ull px = pack2(a.x, a.x), py = pack2(a.y, a.y);
            ull pz = pack2(a.z, a.z), pw = pack2(a.w, a.w);
#pragma unroll
            for (int p = 0; p < 4; p++) {
                fma2(acc[i][p], px, sA[p].x);
                fma2(acc[i][p], py, sA[p].y);
                fma2(acc[i][p], pz, sB[p].x);
                fma2(acc[i][p], pw, sB[p].y);
            }
        }
#pragma unroll
        for (int i = 0; i < 8; i++) cur[i] = nxt[i];
    }

#pragma unroll
    for (int i = 0; i < 8; i++) {
#pragma unroll
        for (int p = 0; p < 4; p++) {
            float x, y;
            unpack2(acc[i][p], x, y);
#pragma unroll
            for (int o = 16; o > 0; o >>= 1) {
                x += __shfl_down_sync(0xFFFFFFFFu, x, o);
                y += __shfl_down_sync(0xFFFFFFFFu, y, o);
            }
            if (lane == 0) {
                g_act[(size_t)(2 * p)     * DIM + (j0 + i)] = sigmoidf(x);
                g_act[(size_t)(2 * p + 1) * DIM + (j0 + i)] = sigmoidf(y);
            }
        }
    }
}

// ---------------- kernel 2/5: per-row top-k ----------------
// phase 0: read g_act -> compact (val, idx) list, sorted by index (per batch).
// phase 1: read g_z2  -> final dense output row (zeros + selected values).
// Exact jax.lax.top_k tie semantics (lowest index wins at the cutoff).
__global__ __launch_bounds__(512) void topk_kernel(float* __restrict__ full_out, int phase) {
    int b   = blockIdx.x;
    int tid = threadIdx.x;
    const float* row = (phase == 0 ? g_act : g_z2) + (size_t)b * DIM;
    const float4* row4 = (const float4*)row;

    uint ub[16];
#pragma unroll
    for (int i = 0; i < 4; i++) {
        float4 v = row4[i * 512 + tid];
        ub[i * 4 + 0] = __float_as_uint(v.x);
        ub[i * 4 + 1] = __float_as_uint(v.y);
        ub[i * 4 + 2] = __float_as_uint(v.z);
        ub[i * 4 + 3] = __float_as_uint(v.w);
    }

    __shared__ int   s_cnt[36];
    __shared__ int   s_tie[64];
    __shared__ float s_outv[64];
    __shared__ int   s_outi[64];
    __shared__ int   s_ntie, s_slot;
    if (tid < 36) s_cnt[tid] = 0;
    if (tid == 0) { s_ntie = 0; s_slot = 0; }

    if (phase == 1) {                // zero output row, overlapped with search
        float4* o4 = (float4*)(full_out + (size_t)b * DIM);
        float4 z = make_float4(0.f, 0.f, 0.f, 0.f);
#pragma unroll
        for (int i = 0; i < 4; i++) o4[i * 512 + tid] = z;
    }
    __syncthreads();

    // binary search over float bits (sigmoid output in (0,1) -> bits monotone)
    uint lo = 0u, hi = 0x3F800001u;
    int it = 0;
    while (hi - lo > 1u) {
        uint mid = lo + ((hi - lo) >> 1);
        int c = 0;
#pragma unroll
        for (int i = 0; i < 16; i++) c += (ub[i] >= mid);
#pragma unroll
        for (int o = 16; o > 0; o >>= 1) c += __shfl_xor_sync(0xFFFFFFFFu, c, o);
        if ((tid & 31) == 0) atomicAdd(&s_cnt[it], c);
        __syncthreads();
        int tot = s_cnt[it];
        it++;
        if (tot >= TOPK) lo = mid; else hi = mid;
    }
    uint T = lo;

    {
        int c = 0;
#pragma unroll
        for (int i = 0; i < 16; i++) c += (ub[i] > T);
#pragma unroll
        for (int o = 16; o > 0; o >>= 1) c += __shfl_xor_sync(0xFFFFFFFFu, c, o);
        if ((tid & 31) == 0) atomicAdd(&s_cnt[33], c);
    }
#pragma unroll
    for (int i = 0; i < 16; i++) {
        if (ub[i] == T) {
            int pos = (i >> 2) * 2048 + tid * 4 + (i & 3);
            int t = atomicAdd(&s_ntie, 1);
            if (t < 64) s_tie[t] = pos;
        }
    }
    __syncthreads();
    int cnt_gt = s_cnt[33];
    int needed = TOPK - cnt_gt;
    int ntie = min(s_ntie, 64);

    if (tid == 0) {
        for (int x = 1; x < ntie; x++) {
            int v = s_tie[x], y = x - 1;
            while (y >= 0 && s_tie[y] > v) { s_tie[y + 1] = s_tie[y]; y--; }
            s_tie[y + 1] = v;
        }
    }
    __syncthreads();
    int nsel = min(needed, 64);

    float* orow = full_out + (size_t)b * DIM;
#pragma unroll
    for (int i = 0; i < 16; i++) {
        uint u = ub[i];
        int pos = (i >> 2) * 2048 + tid * 4 + (i & 3);
        bool take = false;
        if (u > T) {
            take = true;
        } else if (u == T) {
            for (int q = 0; q < nsel; q++) take |= (s_tie[q] == pos);
        }
        if (take) {
            if (phase == 0) {
                int slot = atomicAdd(&s_slot, 1);
                s_outv[slot] = __uint_as_float(u);
                s_outi[slot] = pos;
            } else {
                orow[pos] = __uint_as_float(u);
            }
        }
    }

    if (phase == 0) {
        __syncthreads();
        if (tid < TOPK) {
            int my_i = s_outi[tid];
            float my_v = s_outv[tid];
            int rank = 0;
#pragma unroll 10
            for (int q = 0; q < TOPK; q++) rank += (s_outi[q] < my_i);
            g_vals[b * 64 + rank] = my_v;
            g_idxs[b * 64 + rank] = my_i;
        }
    }
}

// ---------------- kernel 3: merge 8 sorted lists by column ----------------
// key = (col << 3) | b (unique). Per-batch lists are already idx-ascending,
// so global rank = own position + sum of binary-search counts in other lists.
__global__ __launch_bounds__(512) void sort_entries_kernel() {
    __shared__ int s_key[BATCH][64];
    int tid = threadIdx.x;
    for (int t = tid; t < NENT; t += 512) {
        int b = t / TOPK, i = t % TOPK;
        s_key[b][i] = (g_idxs[b * 64 + i] << 3) | b;
    }
    __syncthreads();
    if (tid < NENT) {
        int b = tid / TOPK, i = tid % TOPK;
        int key = s_key[b][i];
        int rank = i;
#pragma unroll
        for (int b2 = 0; b2 < BATCH; b2++) {
            if (b2 == b) continue;
            int lo = 0, len = TOPK;          // count of s_key[b2][*] < key
            while (len > 0) {
                int half = len >> 1;
                int m = lo + half;
                if (s_key[b2][m] < key) { lo = m + 1; len -= half + 1; }
                else len = half;
            }
            rank += lo;
        }
        g_skey[rank] = key;
        g_sval[rank] = g_vals[b * 64 + i];
    }
}

// ---------------- kernel 4: sparse GEMV, warp-per-row coalesced ----------------
// Warp owns row j; lanes sweep the column-sorted merged entry list ->
// consecutive lanes read ascending columns within one row (contiguous DRAM
// windows). Batch separation via 8 predicated accumulators per lane.
__global__ __launch_bounds__(256) void gemv_sparse_kernel(const float* __restrict__ syn) {
    int tid  = threadIdx.x;
    int w    = tid >> 5;
    int lane = tid & 31;
    int j = blockIdx.x * 8 + w;

    __shared__ int   s_key[NENT];
    __shared__ float s_val[NENT];
    for (int t = tid; t < NENT; t += 256) {
        s_key[t] = g_skey[t];
        s_val[t] = g_sval[t];
    }
    __syncthreads();

    const float* __restrict__ row = syn + (size_t)j * DIM;
    float acc[BATCH];
#pragma unroll
    for (int bb = 0; bb < BATCH; bb++) acc[bb] = 0.0f;

#pragma unroll
    for (int i = 0; i < NENT / 32; i++) {             // 15 iterations
        int   key = s_key[i * 32 + lane];
        float v   = s_val[i * 32 + lane];
        float x   = __ldg(&row[key >> 3]);
        float p   = v * x;
        int   b   = key & 7;
#pragma unroll
        for (int bb = 0; bb < BATCH; bb++) {
            acc[bb] += (b == bb) ? p : 0.0f;
        }
    }

#pragma unroll
    for (int o = 16; o > 0; o >>= 1) {
#pragma unroll
        for (int bb = 0; bb < BATCH; bb++) {
            acc[bb] += __shfl_down_sync(0xFFFFFFFFu, acc[bb], o);
        }
    }
    float mine = 0.0f;
#pragma unroll
    for (int bb = 0; bb < BATCH; bb++) {
        float r = __shfl_sync(0xFFFFFFFFu, acc[bb], 0);
        if (lane == bb) mine = r;
    }
    if (lane < BATCH) {
        g_z2[(size_t)lane * DIM + j] = sigmoidf(mine);
    }
}

// ---------------- launch ----------------
extern "C" void kernel_launch(void* const* d_in, const int* in_sizes, int n_in,
                              void* d_out, int out_size) {
    const float* sdr = (const float*)d_in[0];   // [8, 8192]
    const float* syn = (const float*)d_in[1];   // [8192, 8192]
    float* out = (float*)d_out;                 // [8, 8192]
    (void)in_sizes; (void)n_in; (void)out_size;

    pair_sdr_kernel<<<DIM / 256, 256>>>(sdr);
    gemv_dense_kernel<<<DIM / 32, 128>>>(syn);       // 256 blocks, 8 rows/warp
    topk_kernel<<<BATCH, 512>>>(out, /*phase=*/0);   // -> per-batch sorted (val, idx)
    sort_entries_kernel<<<1, 512>>>();               // merge-rank, binary searches
    gemv_sparse_kernel<<<DIM / 8, 256>>>(syn);       // 1024 blocks, warp-per-row
    topk_kernel<<<BATCH, 512>>>(out, /*phase=*/1);   // -> dense output rows
}

// round 8
// speedup vs baseline: 1.0316x; 1.0316x over previous
#include <cuda_runtime.h>
#include <cstdint>
#include <math.h>

#define DIM   8192
#define BATCH 8
#define TOPK  60
#define NENT  (BATCH * TOPK)   // 480 merged sparse entries

typedef unsigned long long ull;
typedef unsigned int uint;

// ---------------- device scratch (no allocations allowed) ----------------
__device__ float g_act[BATCH * DIM];               // step-1 sigmoid output
__device__ float g_z2 [BATCH * DIM];               // step-2 sigmoid output
__device__ ull   g_sdr_paired[(BATCH / 2) * DIM];  // sdr packed as (b,b+1) f32 pairs
__device__ float g_vals[BATCH * 64];               // top-k values, idx-sorted per batch
__device__ int   g_idxs[BATCH * 64];               // top-k indices, ascending per batch

// ---------------- helpers ----------------
__device__ __forceinline__ float sigmoidf(float x) {
    return 1.0f / (1.0f + expf(-x));   // precise expf: selection must match reference
}
__device__ __forceinline__ ull pack2(float x, float y) {
    ull r; asm("mov.b64 %0, {%1,%2};" : "=l"(r) : "f"(x), "f"(y)); return r;
}
__device__ __forceinline__ void unpack2(ull v, float &x, float &y) {
    asm("mov.b64 {%0,%1}, %2;" : "=f"(x), "=f"(y) : "l"(v));
}
__device__ __forceinline__ void fma2(ull &d, ull a, ull b) {
    asm("fma.rn.f32x2 %0, %1, %2, %0;" : "+l"(d) : "l"(a), "l"(b));
}

// ---------------- kernel 0: pack sdr into batch-pairs ----------------
__global__ void pair_sdr_kernel(const float* __restrict__ sdr) {
    int k = blockIdx.x * blockDim.x + threadIdx.x;
    if (k < DIM) {
#pragma unroll
        for (int p = 0; p < BATCH / 2; p++) {
            g_sdr_paired[p * DIM + k] =
                pack2(sdr[(2 * p) * DIM + k], sdr[(2 * p + 1) * DIM + k]);
        }
    }
}

// ---------------- kernel 1: dense GEMV-8 + sigmoid (R6 proven version) ----------------
// Warp owns 4 consecutive rows j; lanes stride over k in float4 units;
// 16 float4 lines in flight per warp body.
__global__ __launch_bounds__(256, 2) void gemv_dense_kernel(const float* __restrict__ syn) {
    int warp = blockIdx.x * 8 + (threadIdx.x >> 5);   // 2048 warps
    int lane = threadIdx.x & 31;
    int j0 = warp * 4;

    const float4* r0 = (const float4*)(syn + (size_t)(j0 + 0) * DIM);
    const float4* r1 = (const float4*)(syn + (size_t)(j0 + 1) * DIM);
    const float4* r2 = (const float4*)(syn + (size_t)(j0 + 2) * DIM);
    const float4* r3 = (const float4*)(syn + (size_t)(j0 + 3) * DIM);

    ull acc[4][4];
#pragma unroll
    for (int i = 0; i < 4; i++)
#pragma unroll
        for (int p = 0; p < 4; p++) acc[i][p] = 0ull;

    for (int t = 0; t < DIM / 4; t += 128) {          // 16 bodies
        float4 a0[4], a1[4], a2[4], a3[4];
#pragma unroll
        for (int u = 0; u < 4; u++) {
            int k4 = t + u * 32 + lane;
            a0[u] = r0[k4]; a1[u] = r1[k4]; a2[u] = r2[k4]; a3[u] = r3[k4];
        }
#pragma unroll
        for (int u = 0; u < 4; u++) {
            int k = (t + u * 32 + lane) * 4;
            ulonglong2 sA[4], sB[4];
#pragma unroll
            for (int p = 0; p < 4; p++) {
                const ulonglong2* sp = (const ulonglong2*)&g_sdr_paired[p * DIM + k];
                sA[p] = sp[0];
                sB[p] = sp[1];
            }
#pragma unroll
            for (int i = 0; i < 4; i++) {
                float4 a = (i == 0 ? a0[u] : i == 1 ? a1[u] : i == 2 ? a2[u] : a3[u]);
                ull px = pack2(a.x, a.x), py = pack2(a.y, a.y);
                ull pz = pack2(a.z, a.z), pw = pack2(a.w, a.w);
#pragma unroll
                for (int p = 0; p < 4; p++) {
                    fma2(acc[i][p], px, sA[p].x);
                    fma2(acc[i][p], py, sA[p].y);
                    fma2(acc[i][p], pz, sB[p].x);
                    fma2(acc[i][p], pw, sB[p].y);
                }
            }
        }
    }

#pragma unroll
    for (int i = 0; i < 4; i++) {
#pragma unroll
        for (int p = 0; p < 4; p++) {
            float x, y;
            unpack2(acc[i][p], x, y);
#pragma unroll
            for (int o = 16; o > 0; o >>= 1) {
                x += __shfl_down_sync(0xFFFFFFFFu, x, o);
                y += __shfl_down_sync(0xFFFFFFFFu, y, o);
            }
            if (lane == 0) {
                g_act[(size_t)(2 * p)     * DIM + (j0 + i)] = sigmoidf(x);
                g_act[(size_t)(2 * p + 1) * DIM + (j0 + i)] = sigmoidf(y);
            }
        }
    }
}

// ---------------- kernel 2/4: per-row top-k ----------------
// phase 0: read g_act -> compact (val, idx) list, sorted by index (per batch).
// phase 1: read g_z2  -> final dense output row (zeros + selected values).
// Exact jax.lax.top_k tie semantics (lowest index wins at the cutoff).
__global__ __launch_bounds__(512) void topk_kernel(float* __restrict__ full_out, int phase) {
    int b   = blockIdx.x;
    int tid = threadIdx.x;
    const float* row = (phase == 0 ? g_act : g_z2) + (size_t)b * DIM;
    const float4* row4 = (const float4*)row;

    uint ub[16];
#pragma unroll
    for (int i = 0; i < 4; i++) {
        float4 v = row4[i * 512 + tid];
        ub[i * 4 + 0] = __float_as_uint(v.x);
        ub[i * 4 + 1] = __float_as_uint(v.y);
        ub[i * 4 + 2] = __float_as_uint(v.z);
        ub[i * 4 + 3] = __float_as_uint(v.w);
    }

    __shared__ int   s_cnt[36];
    __shared__ int   s_tie[64];
    __shared__ float s_outv[64];
    __shared__ int   s_outi[64];
    __shared__ int   s_ntie, s_slot;
    if (tid < 36) s_cnt[tid] = 0;
    if (tid == 0) { s_ntie = 0; s_slot = 0; }

    if (phase == 1) {                // zero output row, overlapped with search
        float4* o4 = (float4*)(full_out + (size_t)b * DIM);
        float4 z = make_float4(0.f, 0.f, 0.f, 0.f);
#pragma unroll
        for (int i = 0; i < 4; i++) o4[i * 512 + tid] = z;
    }
    __syncthreads();

    // binary search over float bits (sigmoid output in (0,1) -> bits monotone)
    uint lo = 0u, hi = 0x3F800001u;
    int it = 0;
    while (hi - lo > 1u) {
        uint mid = lo + ((hi - lo) >> 1);
        int c = 0;
#pragma unroll
        for (int i = 0; i < 16; i++) c += (ub[i] >= mid);
#pragma unroll
        for (int o = 16; o > 0; o >>= 1) c += __shfl_xor_sync(0xFFFFFFFFu, c, o);
        if ((tid & 31) == 0) atomicAdd(&s_cnt[it], c);
        __syncthreads();
        int tot = s_cnt[it];
        it++;
        if (tot >= TOPK) lo = mid; else hi = mid;
    }
    uint T = lo;

    {
        int c = 0;
#pragma unroll
        for (int i = 0; i < 16; i++) c += (ub[i] > T);
#pragma unroll
        for (int o = 16; o > 0; o >>= 1) c += __shfl_xor_sync(0xFFFFFFFFu, c, o);
        if ((tid & 31) == 0) atomicAdd(&s_cnt[33], c);
    }
#pragma unroll
    for (int i = 0; i < 16; i++) {
        if (ub[i] == T) {
            int pos = (i >> 2) * 2048 + tid * 4 + (i & 3);
            int t = atomicAdd(&s_ntie, 1);
            if (t < 64) s_tie[t] = pos;
        }
    }
    __syncthreads();
    int cnt_gt = s_cnt[33];
    int needed = TOPK - cnt_gt;
    int ntie = min(s_ntie, 64);

    if (tid == 0) {
        for (int x = 1; x < ntie; x++) {
            int v = s_tie[x], y = x - 1;
            while (y >= 0 && s_tie[y] > v) { s_tie[y + 1] = s_tie[y]; y--; }
            s_tie[y + 1] = v;
        }
    }
    __syncthreads();
    int nsel = min(needed, 64);

    float* orow = full_out + (size_t)b * DIM;
#pragma unroll
    for (int i = 0; i < 16; i++) {
        uint u = ub[i];
        int pos = (i >> 2) * 2048 + tid * 4 + (i & 3);
        bool take = false;
        if (u > T) {
            take = true;
        } else if (u == T) {
            for (int q = 0; q < nsel; q++) take |= (s_tie[q] == pos);
        }
        if (take) {
            if (phase == 0) {
                int slot = atomicAdd(&s_slot, 1);
                s_outv[slot] = __uint_as_float(u);
                s_outi[slot] = pos;
            } else {
                orow[pos] = __uint_as_float(u);
            }
        }
    }

    if (phase == 0) {
        __syncthreads();
        if (tid < TOPK) {
            int my_i = s_outi[tid];
            float my_v = s_outv[tid];
            int rank = 0;
#pragma unroll 10
            for (int q = 0; q < TOPK; q++) rank += (s_outi[q] < my_i);
            g_vals[b * 64 + rank] = my_v;
            g_idxs[b * 64 + rank] = my_i;
        }
    }
}

// ---------------- kernel 3: sparse GEMV with inlined merge ----------------
// Each block first merge-ranks the 8 per-batch sorted lists into one
// column-ascending list (key = (col<<3)|b) in its own smem — redundant
// per-block work (~700 cyc) hidden under the gather's memory latency.
// Then: warp owns row j; lanes sweep the merged list -> consecutive lanes
// read ascending columns within one row (contiguous DRAM windows).
__global__ __launch_bounds__(256) void gemv_sparse_kernel(const float* __restrict__ syn) {
    int tid  = threadIdx.x;
    int w    = tid >> 5;
    int lane = tid & 31;
    int j = blockIdx.x * 8 + w;

    __shared__ int   s_lk[BATCH][64];     // per-batch keys, idx-ascending
    __shared__ float s_lv[BATCH][64];
    __shared__ int   s_key[NENT];         // merged, column-ascending
    __shared__ float s_val[NENT];

    for (int t = tid; t < BATCH * 64; t += 256) {
        int b = t >> 6, i = t & 63;
        s_lk[b][i] = (g_idxs[t] << 3) | b;   // i>=60 slots never read below
        s_lv[b][i] = g_vals[t];
    }
    __syncthreads();

    // merge-rank: global rank = own position + count of smaller keys elsewhere
    for (int t = tid; t < NENT; t += 256) {
        int b = t / TOPK, i = t - b * TOPK;
        int key = s_lk[b][i];
        int rank = i;
#pragma unroll
        for (int b2 = 0; b2 < BATCH; b2++) {
            if (b2 == b) continue;
            int lo = 0, len = TOPK;
            while (len > 0) {
                int half = len >> 1;
                int m = lo + half;
                if (s_lk[b2][m] < key) { lo = m + 1; len -= half + 1; }
                else len = half;
            }
            rank += lo;
        }
        s_key[rank] = key;
        s_val[rank] = s_lv[b][i];
    }
    __syncthreads();

    const float* __restrict__ row = syn + (size_t)j * DIM;
    float acc[BATCH];
#pragma unroll
    for (int bb = 0; bb < BATCH; bb++) acc[bb] = 0.0f;

#pragma unroll
    for (int i = 0; i < NENT / 32; i++) {             // 15 iterations
        int   key = s_key[i * 32 + lane];
        float v   = s_val[i * 32 + lane];
        float x   = __ldg(&row[key >> 3]);
        float p   = v * x;
        int   b   = key & 7;
#pragma unroll
        for (int bb = 0; bb < BATCH; bb++) {
            acc[bb] += (b == bb) ? p : 0.0f;
        }
    }

#pragma unroll
    for (int o = 16; o > 0; o >>= 1) {
#pragma unroll
        for (int bb = 0; bb < BATCH; bb++) {
            acc[bb] += __shfl_down_sync(0xFFFFFFFFu, acc[bb], o);
        }
    }
    float mine = 0.0f;
#pragma unroll
    for (int bb = 0; bb < BATCH; bb++) {
        float r = __shfl_sync(0xFFFFFFFFu, acc[bb], 0);
        if (lane == bb) mine = r;
    }
    if (lane < BATCH) {
        g_z2[(size_t)lane * DIM + j] = sigmoidf(mine);
    }
}

// ---------------- launch ----------------
extern "C" void kernel_launch(void* const* d_in, const int* in_sizes, int n_in,
                              void* d_out, int out_size) {
    const float* sdr = (const float*)d_in[0];   // [8, 8192]
    const float* syn = (const float*)d_in[1];   // [8192, 8192]
    float* out = (float*)d_out;                 // [8, 8192]
    (void)in_sizes; (void)n_in; (void)out_size;

    pair_sdr_kernel<<<DIM / 256, 256>>>(sdr);
    gemv_dense_kernel<<<DIM / 32, 256>>>(syn);       // 256 blocks, 4 rows/warp
    topk_kernel<<<BATCH, 512>>>(out, /*phase=*/0);   // -> per-batch sorted (val, idx)
    gemv_sparse_kernel<<<DIM / 8, 256>>>(syn);       // 1024 blocks, merge + gather
    topk_kernel<<<BATCH, 512>>>(out, /*phase=*/1);   // -> dense output rows
}

// round 9
// speedup vs baseline: 1.0537x; 1.0214x over previous
#include <cuda_runtime.h>
#include <cstdint>
#include <math.h>

#define DIM   8192
#define BATCH 8
#define TOPK  60
#define NENT  (BATCH * TOPK)   // 480 merged sparse entries
#define CHUNK 2048             // dense-GEMV k-chunk staged in smem
#define NCHUNK (DIM / CHUNK)   // 4
#define DENSE_SMEM (4 * CHUNK * 8)   // 64 KB: 4 pair-arrays x 2048 x 8B

typedef unsigned long long ull;
typedef unsigned int uint;

// ---------------- device scratch (no allocations allowed) ----------------
__device__ float g_act[BATCH * DIM];               // step-1 sigmoid output
__device__ float g_z2 [BATCH * DIM];               // step-2 sigmoid output
__device__ float g_vals[BATCH * 64];               // top-k values, idx-sorted per batch
__device__ int   g_idxs[BATCH * 64];               // top-k indices, ascending per batch

// ---------------- helpers ----------------
__device__ __forceinline__ float sigmoidf(float x) {
    return 1.0f / (1.0f + expf(-x));   // precise expf: selection must match reference
}
__device__ __forceinline__ ull pack2(float x, float y) {
    ull r; asm("mov.b64 %0, {%1,%2};" : "=l"(r) : "f"(x), "f"(y)); return r;
}
__device__ __forceinline__ void unpack2(ull v, float &x, float &y) {
    asm("mov.b64 {%0,%1}, %2;" : "=f"(x), "=f"(y) : "l"(v));
}
__device__ __forceinline__ void fma2(ull &d, ull a, ull b) {
    asm("fma.rn.f32x2 %0, %1, %2, %0;" : "+l"(d) : "l"(a), "l"(b));
}

// ---------------- kernel 1: dense GEMV-8 + sigmoid, smem-staged sdr ----------------
// Warp owns 4 consecutive rows j. k is processed in 4 chunks of 2048: the
// block cooperatively packs sdr batch-pairs for the chunk into smem (64 KB),
// then warps stream syn (float4 LDG, 16 lines in flight) while reading sdr
// via conflict-free LDS.128. Cuts sdr L2 traffic 512 MB -> 64 MB.
// FMA order per lane identical to the unchunked version (bit-exact).
__global__ __launch_bounds__(256, 2) void gemv_dense_kernel(
        const float* __restrict__ syn, const float* __restrict__ sdr) {
    extern __shared__ __align__(16) ull s_sdr[];   // [4][CHUNK]
    int tid  = threadIdx.x;
    int warp = blockIdx.x * 8 + (tid >> 5);        // 2048 warps
    int lane = tid & 31;
    int j0 = warp * 4;

    const float4* r0 = (const float4*)(syn + (size_t)(j0 + 0) * DIM);
    const float4* r1 = (const float4*)(syn + (size_t)(j0 + 1) * DIM);
    const float4* r2 = (const float4*)(syn + (size_t)(j0 + 2) * DIM);
    const float4* r3 = (const float4*)(syn + (size_t)(j0 + 3) * DIM);

    ull acc[4][4];
#pragma unroll
    for (int i = 0; i < 4; i++)
#pragma unroll
        for (int p = 0; p < 4; p++) acc[i][p] = 0ull;

    for (int c = 0; c < NCHUNK; c++) {
        int c0 = c * CHUNK;          // chunk base (float index)
        int g4 = c0 / 4;             // chunk base (float4 index)

        __syncthreads();             // previous chunk's LDS reads done
        // stage: pack sdr pairs for this chunk into smem (float4 granular)
        for (int t4 = tid; t4 < CHUNK / 4; t4 += 256) {
#pragma unroll
            for (int p = 0; p < 4; p++) {
                float4 lo = ((const float4*)(sdr + (size_t)(2 * p)     * DIM))[g4 + t4];
                float4 hi = ((const float4*)(sdr + (size_t)(2 * p + 1) * DIM))[g4 + t4];
                ull* d = &s_sdr[p * CHUNK + t4 * 4];
                d[0] = pack2(lo.x, hi.x);
                d[1] = pack2(lo.y, hi.y);
                d[2] = pack2(lo.z, hi.z);
                d[3] = pack2(lo.w, hi.w);
            }
        }
        __syncthreads();

        for (int t = 0; t < CHUNK / 4; t += 128) {   // 4 bodies per chunk
            float4 a0[4], a1[4], a2[4], a3[4];
#pragma unroll
            for (int u = 0; u < 4; u++) {
                int k4 = g4 + t + u * 32 + lane;
                a0[u] = r0[k4]; a1[u] = r1[k4]; a2[u] = r2[k4]; a3[u] = r3[k4];
            }
#pragma unroll
            for (int u = 0; u < 4; u++) {
                int kk = (t + u * 32 + lane) * 4;    // pair index within chunk
                ulonglong2 sA[4], sB[4];
#pragma unroll
                for (int p = 0; p < 4; p++) {
                    const ulonglong2* sp = (const ulonglong2*)&s_sdr[p * CHUNK + kk];
                    sA[p] = sp[0];
                    sB[p] = sp[1];
                }
#pragma unroll
                for (int i = 0; i < 4; i++) {
                    float4 a = (i == 0 ? a0[u] : i == 1 ? a1[u] : i == 2 ? a2[u] : a3[u]);
                    ull px = pack2(a.x, a.x), py = pack2(a.y, a.y);
                    ull pz = pack2(a.z, a.z), pw = pack2(a.w, a.w);
#pragma unroll
                    for (int p = 0; p < 4; p++) {
                        fma2(acc[i][p], px, sA[p].x);
                        fma2(acc[i][p], py, sA[p].y);
                        fma2(acc[i][p], pz, sB[p].x);
                        fma2(acc[i][p], pw, sB[p].y);
                    }
                }
            }
        }
    }

#pragma unroll
    for (int i = 0; i < 4; i++) {
#pragma unroll
        for (int p = 0; p < 4; p++) {
            float x, y;
            unpack2(acc[i][p], x, y);
#pragma unroll
            for (int o = 16; o > 0; o >>= 1) {
                x += __shfl_down_sync(0xFFFFFFFFu, x, o);
                y += __shfl_down_sync(0xFFFFFFFFu, y, o);
            }
            if (lane == 0) {
                g_act[(size_t)(2 * p)     * DIM + (j0 + i)] = sigmoidf(x);
                g_act[(size_t)(2 * p + 1) * DIM + (j0 + i)] = sigmoidf(y);
            }
        }
    }
}

// ---------------- kernel 2/4: per-row top-k ----------------
// phase 0: read g_act -> compact (val, idx) list, sorted by index (per batch).
// phase 1: read g_z2  -> final dense output row (zeros + selected values).
// Exact jax.lax.top_k tie semantics (lowest index wins at the cutoff).
__global__ __launch_bounds__(512) void topk_kernel(float* __restrict__ full_out, int phase) {
    int b   = blockIdx.x;
    int tid = threadIdx.x;
    const float* row = (phase == 0 ? g_act : g_z2) + (size_t)b * DIM;
    const float4* row4 = (const float4*)row;

    uint ub[16];
#pragma unroll
    for (int i = 0; i < 4; i++) {
        float4 v = row4[i * 512 + tid];
        ub[i * 4 + 0] = __float_as_uint(v.x);
        ub[i * 4 + 1] = __float_as_uint(v.y);
        ub[i * 4 + 2] = __float_as_uint(v.z);
        ub[i * 4 + 3] = __float_as_uint(v.w);
    }

    __shared__ int   s_cnt[36];
    __shared__ int   s_tie[64];
    __shared__ float s_outv[64];
    __shared__ int   s_outi[64];
    __shared__ int   s_ntie, s_slot;
    if (tid < 36) s_cnt[tid] = 0;
    if (tid == 0) { s_ntie = 0; s_slot = 0; }

    if (phase == 1) {                // zero output row, overlapped with search
        float4* o4 = (float4*)(full_out + (size_t)b * DIM);
        float4 z = make_float4(0.f, 0.f, 0.f, 0.f);
#pragma unroll
        for (int i = 0; i < 4; i++) o4[i * 512 + tid] = z;
    }
    __syncthreads();

    // binary search over float bits (sigmoid output in (0,1) -> bits monotone)
    uint lo = 0u, hi = 0x3F800001u;
    int it = 0;
    while (hi - lo > 1u) {
        uint mid = lo + ((hi - lo) >> 1);
        int c = 0;
#pragma unroll
        for (int i = 0; i < 16; i++) c += (ub[i] >= mid);
#pragma unroll
        for (int o = 16; o > 0; o >>= 1) c += __shfl_xor_sync(0xFFFFFFFFu, c, o);
        if ((tid & 31) == 0) atomicAdd(&s_cnt[it], c);
        __syncthreads();
        int tot = s_cnt[it];
        it++;
        if (tot >= TOPK) lo = mid; else hi = mid;
    }
    uint T = lo;

    {
        int c = 0;
#pragma unroll
        for (int i = 0; i < 16; i++) c += (ub[i] > T);
#pragma unroll
        for (int o = 16; o > 0; o >>= 1) c += __shfl_xor_sync(0xFFFFFFFFu, c, o);
        if ((tid & 31) == 0) atomicAdd(&s_cnt[33], c);
    }
#pragma unroll
    for (int i = 0; i < 16; i++) {
        if (ub[i] == T) {
            int pos = (i >> 2) * 2048 + tid * 4 + (i & 3);
            int t = atomicAdd(&s_ntie, 1);
            if (t < 64) s_tie[t] = pos;
        }
    }
    __syncthreads();
    int cnt_gt = s_cnt[33];
    int needed = TOPK - cnt_gt;
    int ntie = min(s_ntie, 64);

    if (tid == 0) {
        for (int x = 1; x < ntie; x++) {
            int v = s_tie[x], y = x - 1;
            while (y >= 0 && s_tie[y] > v) { s_tie[y + 1] = s_tie[y]; y--; }
            s_tie[y + 1] = v;
        }
    }
    __syncthreads();
    int nsel = min(needed, 64);

    float* orow = full_out + (size_t)b * DIM;
#pragma unroll
    for (int i = 0; i < 16; i++) {
        uint u = ub[i];
        int pos = (i >> 2) * 2048 + tid * 4 + (i & 3);
        bool take = false;
        if (u > T) {
            take = true;
        } else if (u == T) {
            for (int q = 0; q < nsel; q++) take |= (s_tie[q] == pos);
        }
        if (take) {
            if (phase == 0) {
                int slot = atomicAdd(&s_slot, 1);
                s_outv[slot] = __uint_as_float(u);
                s_outi[slot] = pos;
            } else {
                orow[pos] = __uint_as_float(u);
            }
        }
    }

    if (phase == 0) {
        __syncthreads();
        if (tid < TOPK) {
            int my_i = s_outi[tid];
            float my_v = s_outv[tid];
            int rank = 0;
#pragma unroll 10
            for (int q = 0; q < TOPK; q++) rank += (s_outi[q] < my_i);
            g_vals[b * 64 + rank] = my_v;
            g_idxs[b * 64 + rank] = my_i;
        }
    }
}

// ---------------- kernel 3: sparse GEMV with inlined merge ----------------
// Each block merge-ranks the 8 per-batch sorted lists into one column-
// ascending list (key = (col<<3)|b) in smem, then: warp owns row j; lanes
// sweep the merged list -> consecutive lanes read ascending columns within
// one row (contiguous DRAM windows). 8 predicated accs per lane.
__global__ __launch_bounds__(256) void gemv_sparse_kernel(const float* __restrict__ syn) {
    int tid  = threadIdx.x;
    int w    = tid >> 5;
    int lane = tid & 31;
    int j = blockIdx.x * 8 + w;

    __shared__ int   s_lk[BATCH][64];     // per-batch keys, idx-ascending
    __shared__ float s_lv[BATCH][64];
    __shared__ int   s_key[NENT];         // merged, column-ascending
    __shared__ float s_val[NENT];

    for (int t = tid; t < BATCH * 64; t += 256) {
        int b = t >> 6, i = t & 63;
        s_lk[b][i] = (g_idxs[t] << 3) | b;   // i>=60 slots never read below
        s_lv[b][i] = g_vals[t];
    }
    __syncthreads();

    for (int t = tid; t < NENT; t += 256) {
        int b = t / TOPK, i = t - b * TOPK;
        int key = s_lk[b][i];
        int rank = i;
#pragma unroll
        for (int b2 = 0; b2 < BATCH; b2++) {
            if (b2 == b) continue;
            int lo = 0, len = TOPK;
            while (len > 0) {
                int half = len >> 1;
                int m = lo + half;
                if (s_lk[b2][m] < key) { lo = m + 1; len -= half + 1; }
                else len = half;
            }
            rank += lo;
        }
        s_key[rank] = key;
        s_val[rank] = s_lv[b][i];
    }
    __syncthreads();

    const float* __restrict__ row = syn + (size_t)j * DIM;
    float acc[BATCH];
#pragma unroll
    for (int bb = 0; bb < BATCH; bb++) acc[bb] = 0.0f;

#pragma unroll
    for (int i = 0; i < NENT / 32; i++) {             // 15 iterations
        int   key = s_key[i * 32 + lane];
        float v   = s_val[i * 32 + lane];
        float x   = __ldg(&row[key >> 3]);
        float p   = v * x;
        int   b   = key & 7;
#pragma unroll
        for (int bb = 0; bb < BATCH; bb++) {
            acc[bb] += (b == bb) ? p : 0.0f;
        }
    }

#pragma unroll
    for (int o = 16; o > 0; o >>= 1) {
#pragma unroll
        for (int bb = 0; bb < BATCH; bb++) {
            acc[bb] += __shfl_down_sync(0xFFFFFFFFu, acc[bb], o);
        }
    }
    float mine = 0.0f;
#pragma unroll
    for (int bb = 0; bb < BATCH; bb++) {
        float r = __shfl_sync(0xFFFFFFFFu, acc[bb], 0);
        if (lane == bb) mine = r;
    }
    if (lane < BATCH) {
        g_z2[(size_t)lane * DIM + j] = sigmoidf(mine);
    }
}

// ---------------- launch ----------------
extern "C" void kernel_launch(void* const* d_in, const int* in_sizes, int n_in,
                              void* d_out, int out_size) {
    const float* sdr = (const float*)d_in[0];   // [8, 8192]
    const float* syn = (const float*)d_in[1];   // [8192, 8192]
    float* out = (float*)d_out;                 // [8, 8192]
    (void)in_sizes; (void)n_in; (void)out_size;

    static int smem_set = 0;
    if (!smem_set) {
        cudaFuncSetAttribute(gemv_dense_kernel,
                             cudaFuncAttributeMaxDynamicSharedMemorySize, DENSE_SMEM);
        smem_set = 1;
    }

    gemv_dense_kernel<<<DIM / 32, 256, DENSE_SMEM>>>(syn, sdr);  // 256 blocks
    topk_kernel<<<BATCH, 512>>>(out, /*phase=*/0);   // -> per-batch sorted (val, idx)
    gemv_sparse_kernel<<<DIM / 8, 256>>>(syn);       // 1024 blocks, merge + gather
    topk_kernel<<<BATCH, 512>>>(out, /*phase=*/1);   // -> dense output rows
}

// round 10
// speedup vs baseline: 1.1830x; 1.1227x over previous
#include <cuda_runtime.h>
#include <cstdint>
#include <math.h>

#define DIM   8192
#define BATCH 8
#define TOPK  60
#define NENT  (BATCH * TOPK)   // 480 merged sparse entries
#define CHUNK 2048             // dense-GEMV k-chunk staged in smem
#define NCHUNK (DIM / CHUNK)   // 4
#define DENSE_SMEM (4 * CHUNK * 8)   // 64 KB
#define NBINS 2048
#define CCAP  128              // candidate cap before fallback

typedef unsigned long long ull;
typedef unsigned int uint;

// ---------------- device scratch (no allocations allowed) ----------------
__device__ float g_act[BATCH * DIM];               // step-1 sigmoid output
__device__ float g_z2 [BATCH * DIM];               // step-2 sigmoid output
__device__ float g_vals[BATCH * 64];               // top-k values, idx-sorted per batch
__device__ int   g_idxs[BATCH * 64];               // top-k indices, ascending per batch

// ---------------- helpers ----------------
__device__ __forceinline__ float sigmoidf(float x) {
    return 1.0f / (1.0f + expf(-x));   // precise expf: selection must match reference
}
__device__ __forceinline__ ull pack2(float x, float y) {
    ull r; asm("mov.b64 %0, {%1,%2};" : "=l"(r) : "f"(x), "f"(y)); return r;
}
__device__ __forceinline__ void unpack2(ull v, float &x, float &y) {
    asm("mov.b64 {%0,%1}, %2;" : "=f"(x), "=f"(y) : "l"(v));
}
__device__ __forceinline__ void fma2(ull &d, ull a, ull b) {
    asm("fma.rn.f32x2 %0, %1, %2, %0;" : "+l"(d) : "l"(a), "l"(b));
}

// ---------------- kernel 1: dense GEMV-8 + sigmoid, smem-staged sdr ----------------
__global__ __launch_bounds__(256, 2) void gemv_dense_kernel(
        const float* __restrict__ syn, const float* __restrict__ sdr) {
    extern __shared__ __align__(16) ull s_sdr[];   // [4][CHUNK]
    int tid  = threadIdx.x;
    int warp = blockIdx.x * 8 + (tid >> 5);        // 2048 warps
    int lane = tid & 31;
    int j0 = warp * 4;

    const float4* r0 = (const float4*)(syn + (size_t)(j0 + 0) * DIM);
    const float4* r1 = (const float4*)(syn + (size_t)(j0 + 1) * DIM);
    const float4* r2 = (const float4*)(syn + (size_t)(j0 + 2) * DIM);
    const float4* r3 = (const float4*)(syn + (size_t)(j0 + 3) * DIM);

    ull acc[4][4];
#pragma unroll
    for (int i = 0; i < 4; i++)
#pragma unroll
        for (int p = 0; p < 4; p++) acc[i][p] = 0ull;

    for (int c = 0; c < NCHUNK; c++) {
        int g4 = c * CHUNK / 4;

        __syncthreads();
        for (int t4 = tid; t4 < CHUNK / 4; t4 += 256) {
#pragma unroll
            for (int p = 0; p < 4; p++) {
                float4 lo = ((const float4*)(sdr + (size_t)(2 * p)     * DIM))[g4 + t4];
                float4 hi = ((const float4*)(sdr + (size_t)(2 * p + 1) * DIM))[g4 + t4];
                ull* d = &s_sdr[p * CHUNK + t4 * 4];
                d[0] = pack2(lo.x, hi.x);
                d[1] = pack2(lo.y, hi.y);
                d[2] = pack2(lo.z, hi.z);
                d[3] = pack2(lo.w, hi.w);
            }
        }
        __syncthreads();

        for (int t = 0; t < CHUNK / 4; t += 128) {
            float4 a0[4], a1[4], a2[4], a3[4];
#pragma unroll
            for (int u = 0; u < 4; u++) {
                int k4 = g4 + t + u * 32 + lane;
                a0[u] = r0[k4]; a1[u] = r1[k4]; a2[u] = r2[k4]; a3[u] = r3[k4];
            }
#pragma unroll
            for (int u = 0; u < 4; u++) {
                int kk = (t + u * 32 + lane) * 4;
                ulonglong2 sA[4], sB[4];
#pragma unroll
                for (int p = 0; p < 4; p++) {
                    const ulonglong2* sp = (const ulonglong2*)&s_sdr[p * CHUNK + kk];
                    sA[p] = sp[0];
                    sB[p] = sp[1];
                }
#pragma unroll
                for (int i = 0; i < 4; i++) {
                    float4 a = (i == 0 ? a0[u] : i == 1 ? a1[u] : i == 2 ? a2[u] : a3[u]);
                    ull px = pack2(a.x, a.x), py = pack2(a.y, a.y);
                    ull pz = pack2(a.z, a.z), pw = pack2(a.w, a.w);
#pragma unroll
                    for (int p = 0; p < 4; p++) {
                        fma2(acc[i][p], px, sA[p].x);
                        fma2(acc[i][p], py, sA[p].y);
                        fma2(acc[i][p], pz, sB[p].x);
                        fma2(acc[i][p], pw, sB[p].y);
                    }
                }
            }
        }
    }

#pragma unroll
    for (int i = 0; i < 4; i++) {
#pragma unroll
        for (int p = 0; p < 4; p++) {
            float x, y;
            unpack2(acc[i][p], x, y);
#pragma unroll
            for (int o = 16; o > 0; o >>= 1) {
                x += __shfl_down_sync(0xFFFFFFFFu, x, o);
                y += __shfl_down_sync(0xFFFFFFFFu, y, o);
            }
            if (lane == 0) {
                g_act[(size_t)(2 * p)     * DIM + (j0 + i)] = sigmoidf(x);
                g_act[(size_t)(2 * p + 1) * DIM + (j0 + i)] = sigmoidf(y);
            }
        }
    }
}

// ---------------- kernel 2/4: per-row top-k via histogram select ----------------
// phase 0: read g_act -> compact (val, idx) list, sorted by index (per batch).
// phase 1: read g_z2  -> final dense output row (zeros + selected values).
// Primary path: values>=0.5 histogrammed into 2048 bins, suffix scan finds
// the threshold bin, tiny candidate sort gives exact T + tie list.
// Exact jax.lax.top_k tie semantics (lowest index wins at the cutoff).
// Fallbacks (threshold < 0.5 or too many candidates) use a bit-binary search.
__global__ __launch_bounds__(512) void topk_kernel(float* __restrict__ full_out, int phase) {
    int b    = blockIdx.x;
    int tid  = threadIdx.x;
    int lane = tid & 31;
    int wid  = tid >> 5;
    const float* row = (phase == 0 ? g_act : g_z2) + (size_t)b * DIM;
    const float4* row4 = (const float4*)row;

    uint ub[16];
#pragma unroll
    for (int i = 0; i < 4; i++) {
        float4 v = row4[i * 512 + tid];
        ub[i * 4 + 0] = __float_as_uint(v.x);
        ub[i * 4 + 1] = __float_as_uint(v.y);
        ub[i * 4 + 2] = __float_as_uint(v.z);
        ub[i * 4 + 3] = __float_as_uint(v.w);
    }

    __shared__ uint  s_h[NBINS];
    __shared__ int   s_wsum[16], s_wsuf[16];
    __shared__ int   s_B, s_cntgt, s_nc, s_c05;
    __shared__ uint  s_Tsh;
    __shared__ int   s_nselsh;
    __shared__ uint  s_cb[CCAP];
    __shared__ int   s_cp[CCAP];
    __shared__ int   s_tie[64];
    __shared__ float s_outv[64];
    __shared__ int   s_outi[64];
    __shared__ int   s_cnt[40];
    __shared__ int   s_ntie, s_slot;

#pragma unroll
    for (int q = 0; q < NBINS / 512; q++) s_h[q * 512 + tid] = 0u;
    if (tid < 40) s_cnt[tid] = 0;
    if (tid == 0) { s_nc = 0; s_c05 = 0; s_ntie = 0; s_slot = 0; }

    if (phase == 1) {                // zero output row (ordered by later barriers)
        float4* o4 = (float4*)(full_out + (size_t)b * DIM);
        float4 z = make_float4(0.f, 0.f, 0.f, 0.f);
#pragma unroll
        for (int i = 0; i < 4; i++) o4[i * 512 + tid] = z;
    }
    __syncthreads();

    // count >= 0.5 and histogram the upper half
    {
        int c = 0;
#pragma unroll
        for (int i = 0; i < 16; i++) c += (ub[i] >= 0x3F000000u);
#pragma unroll
        for (int o = 16; o > 0; o >>= 1) c += __shfl_xor_sync(0xFFFFFFFFu, c, o);
        if (lane == 0) atomicAdd(&s_c05, c);
#pragma unroll
        for (int i = 0; i < 16; i++) {
            if (ub[i] >= 0x3F000000u) {
                uint bin = min((uint)(NBINS - 1), (ub[i] - 0x3F000000u) >> 12);
                atomicAdd(&s_h[bin], 1u);
            }
        }
    }
    __syncthreads();

    uint T = 0;
    int  nsel = 0;
    bool primary = (s_c05 >= TOPK);

    if (primary) {
        // suffix scan over 2048 bins (4 per thread)
        uint h0 = s_h[tid * 4 + 0], h1 = s_h[tid * 4 + 1];
        uint h2 = s_h[tid * 4 + 2], h3 = s_h[tid * 4 + 3];
        int local = (int)(h0 + h1 + h2 + h3);
        int x = local;
#pragma unroll
        for (int o = 1; o < 32; o <<= 1) {
            int v = __shfl_down_sync(0xFFFFFFFFu, x, o);
            if (lane + o < 32) x += v;
        }
        if (lane == 0) s_wsum[wid] = x;        // warp total
        __syncthreads();
        if (wid == 0) {
            int w = s_wsum[lane & 15];
#pragma unroll
            for (int o = 1; o < 16; o <<= 1) {
                int v = __shfl_down_sync(0xFFFFFFFFu, w, o);
                if (lane + o < 16) w += v;
            }
            if (lane < 16) s_wsuf[lane] = w;   // suffix over warps >= lane
        }
        __syncthreads();
        int incl = x + ((wid < 15) ? s_wsuf[wid + 1] : 0);  // suffix over threads >= tid
        int excl = incl - local;                             // suffix over threads >  tid
        int c3 = excl + (int)h3;
        int c2 = c3 + (int)h2;
        int c1 = c2 + (int)h1;
        int c0 = c1 + (int)h0;
        // boundary: cum(bin) >= K, cum(bin+1) < K  (unique)
        if (c0 >= TOPK && c1 < TOPK) { s_B = tid * 4 + 0; s_cntgt = c1; }
        if (c1 >= TOPK && c2 < TOPK) { s_B = tid * 4 + 1; s_cntgt = c2; }
        if (c2 >= TOPK && c3 < TOPK) { s_B = tid * 4 + 2; s_cntgt = c3; }
        if (c3 >= TOPK && excl < TOPK) { s_B = tid * 4 + 3; s_cntgt = excl; }
        __syncthreads();
        int B = s_B, cnt_gt = s_cntgt;

        // gather candidates in bin B
#pragma unroll
        for (int i = 0; i < 16; i++) {
            if (ub[i] >= 0x3F000000u) {
                uint bin = min((uint)(NBINS - 1), (ub[i] - 0x3F000000u) >> 12);
                if ((int)bin == B) {
                    int t = atomicAdd(&s_nc, 1);
                    if (t < CCAP) {
                        s_cb[t] = ub[i];
                        s_cp[t] = (i >> 2) * 2048 + tid * 4 + (i & 3);
                    }
                }
            }
        }
        __syncthreads();
        int nc = s_nc;
        if (nc <= CCAP) {
            if (tid == 0) {
                // insertion sort: bits desc, pos asc for equal bits
                for (int q = 1; q < nc; q++) {
                    uint vb = s_cb[q]; int vp = s_cp[q];
                    int y = q - 1;
                    while (y >= 0 && (s_cb[y] < vb || (s_cb[y] == vb && s_cp[y] > vp))) {
                        s_cb[y + 1] = s_cb[y]; s_cp[y + 1] = s_cp[y]; y--;
                    }
                    s_cb[y + 1] = vb; s_cp[y + 1] = vp;
                }
                int need = TOPK - cnt_gt;          // 1 <= need <= nc
                uint Tv = s_cb[need - 1];
                int first = 0;
                while (s_cb[first] != Tv) first++;
                int ns = need - first;             // accepted ties, lowest pos first
                if (ns > 64) ns = 64;
                for (int q = 0; q < ns; q++) s_tie[q] = s_cp[first + q];
                s_Tsh = Tv;
                s_nselsh = ns;
            }
            __syncthreads();
            T = s_Tsh;
            nsel = s_nselsh;
        } else {
            primary = false;
        }
    }

    if (!primary) {
        // fallback: binary search over float bits + old tie machinery
        uint lo = 0u, hi = 0x3F800001u;
        int it = 0;
        while (hi - lo > 1u) {
            uint mid = lo + ((hi - lo) >> 1);
            int c = 0;
#pragma unroll
            for (int i = 0; i < 16; i++) c += (ub[i] >= mid);
#pragma unroll
            for (int o = 16; o > 0; o >>= 1) c += __shfl_xor_sync(0xFFFFFFFFu, c, o);
            if (lane == 0) atomicAdd(&s_cnt[it], c);
            __syncthreads();
            int tot = s_cnt[it];
            it++;
            if (tot >= TOPK) lo = mid; else hi = mid;
        }
        T = lo;
        {
            int c = 0;
#pragma unroll
            for (int i = 0; i < 16; i++) c += (ub[i] > T);
#pragma unroll
            for (int o = 16; o > 0; o >>= 1) c += __shfl_xor_sync(0xFFFFFFFFu, c, o);
            if (lane == 0) atomicAdd(&s_cnt[33], c);
        }
#pragma unroll
        for (int i = 0; i < 16; i++) {
            if (ub[i] == T) {
                int pos = (i >> 2) * 2048 + tid * 4 + (i & 3);
                int t = atomicAdd(&s_ntie, 1);
                if (t < 64) s_tie[t] = pos;
            }
        }
        __syncthreads();
        int cnt_gt = s_cnt[33];
        int needed = TOPK - cnt_gt;
        int ntie = min(s_ntie, 64);
        if (tid == 0) {
            for (int q = 1; q < ntie; q++) {
                int v = s_tie[q], y = q - 1;
                while (y >= 0 && s_tie[y] > v) { s_tie[y + 1] = s_tie[y]; y--; }
                s_tie[y + 1] = v;
            }
        }
        __syncthreads();
        nsel = min(needed, 64);
    }

    // ---- selection pass (common) ----
    float* orow = full_out + (size_t)b * DIM;
#pragma unroll
    for (int i = 0; i < 16; i++) {
        uint u = ub[i];
        int pos = (i >> 2) * 2048 + tid * 4 + (i & 3);
        bool take = false;
        if (u > T) {
            take = true;
        } else if (u == T) {
            for (int q = 0; q < nsel; q++) take |= (s_tie[q] == pos);
        }
        if (take) {
            if (phase == 0) {
                int slot = atomicAdd(&s_slot, 1);
                s_outv[slot] = __uint_as_float(u);
                s_outi[slot] = pos;
            } else {
                orow[pos] = __uint_as_float(u);
            }
        }
    }

    if (phase == 0) {
        __syncthreads();
        if (tid < TOPK) {
            int my_i = s_outi[tid];
            float my_v = s_outv[tid];
            int rank = 0;
#pragma unroll 10
            for (int q = 0; q < TOPK; q++) rank += (s_outi[q] < my_i);
            g_vals[b * 64 + rank] = my_v;
            g_idxs[b * 64 + rank] = my_i;
        }
    }
}

// ---------------- kernel 3: sparse GEMV with inlined merge ----------------
__global__ __launch_bounds__(256) void gemv_sparse_kernel(const float* __restrict__ syn) {
    int tid  = threadIdx.x;
    int w    = tid >> 5;
    int lane = tid & 31;
    int j = blockIdx.x * 8 + w;

    __shared__ int   s_lk[BATCH][64];
    __shared__ float s_lv[BATCH][64];
    __shared__ int   s_key[NENT];
    __shared__ float s_val[NENT];

    for (int t = tid; t < BATCH * 64; t += 256) {
        int b = t >> 6, i = t & 63;
        s_lk[b][i] = (g_idxs[t] << 3) | b;
        s_lv[b][i] = g_vals[t];
    }
    __syncthreads();

    for (int t = tid; t < NENT; t += 256) {
        int b = t / TOPK, i = t - b * TOPK;
        int key = s_lk[b][i];
        int rank = i;
#pragma unroll
        for (int b2 = 0; b2 < BATCH; b2++) {
            if (b2 == b) continue;
            int lo = 0, len = TOPK;
            while (len > 0) {
                int half = len >> 1;
                int m = lo + half;
                if (s_lk[b2][m] < key) { lo = m + 1; len -= half + 1; }
                else len = half;
            }
            rank += lo;
        }
        s_key[rank] = key;
        s_val[rank] = s_lv[b][i];
    }
    __syncthreads();

    const float* __restrict__ row = syn + (size_t)j * DIM;
    float acc[BATCH];
#pragma unroll
    for (int bb = 0; bb < BATCH; bb++) acc[bb] = 0.0f;

#pragma unroll
    for (int i = 0; i < NENT / 32; i++) {
        int   key = s_key[i * 32 + lane];
        float v   = s_val[i * 32 + lane];
        float x   = __ldg(&row[key >> 3]);
        float p   = v * x;
        int   b   = key & 7;
#pragma unroll
        for (int bb = 0; bb < BATCH; bb++) {
            acc[bb] += (b == bb) ? p : 0.0f;
        }
    }

#pragma unroll
    for (int o = 16; o > 0; o >>= 1) {
#pragma unroll
        for (int bb = 0; bb < BATCH; bb++) {
            acc[bb] += __shfl_down_sync(0xFFFFFFFFu, acc[bb], o);
        }
    }
    float mine = 0.0f;
#pragma unroll
    for (int bb = 0; bb < BATCH; bb++) {
        float r = __shfl_sync(0xFFFFFFFFu, acc[bb], 0);
        if (lane == bb) mine = r;
    }
    if (lane < BATCH) {
        g_z2[(size_t)lane * DIM + j] = sigmoidf(mine);
    }
}

// ---------------- launch ----------------
extern "C" void kernel_launch(void* const* d_in, const int* in_sizes, int n_in,
                              void* d_out, int out_size) {
    const float* sdr = (const float*)d_in[0];   // [8, 8192]
    const float* syn = (const float*)d_in[1];   // [8192, 8192]
    float* out = (float*)d_out;                 // [8, 8192]
    (void)in_sizes; (void)n_in; (void)out_size;

    static int smem_set = 0;
    if (!smem_set) {
        cudaFuncSetAttribute(gemv_dense_kernel,
                             cudaFuncAttributeMaxDynamicSharedMemorySize, DENSE_SMEM);
        smem_set = 1;
    }

    gemv_dense_kernel<<<DIM / 32, 256, DENSE_SMEM>>>(syn, sdr);  // 256 blocks
    topk_kernel<<<BATCH, 512>>>(out, /*phase=*/0);   // -> per-batch sorted (val, idx)
    gemv_sparse_kernel<<<DIM / 8, 256>>>(syn);       // 1024 blocks, merge + gather
    topk_kernel<<<BATCH, 512>>>(out, /*phase=*/1);   // -> dense output rows
}

// round 11
// speedup vs baseline: 1.2722x; 1.0754x over previous
#include <cuda_runtime.h>
#include <cstdint>
#include <math.h>

#define DIM   8192
#define BATCH 8
#define TOPK  60
#define CHUNK 2048             // dense-GEMV k-chunk staged in smem
#define NCHUNK (DIM / CHUNK)   // 4
#define DENSE_SMEM (4 * CHUNK * 8)   // 64 KB
#define NBINS 2048
#define CCAP  128              // candidate cap before fallback
#define TK_THREADS 1024

typedef unsigned long long ull;
typedef unsigned int uint;

// ---------------- device scratch (no allocations allowed) ----------------
__device__ float g_act[BATCH * DIM];               // step-1 sigmoid output
__device__ float g_z2 [BATCH * DIM];               // step-2 sigmoid output
__device__ float g_vals[BATCH * 64];               // top-k values, idx-sorted, 0-padded to 64
__device__ int   g_idxs[BATCH * 64];               // top-k indices, ascending, 0-padded

// ---------------- helpers ----------------
__device__ __forceinline__ float sigmoidf(float x) {
    return 1.0f / (1.0f + expf(-x));   // precise expf: selection must match reference
}
__device__ __forceinline__ ull pack2(float x, float y) {
    ull r; asm("mov.b64 %0, {%1,%2};" : "=l"(r) : "f"(x), "f"(y)); return r;
}
__device__ __forceinline__ void unpack2(ull v, float &x, float &y) {
    asm("mov.b64 {%0,%1}, %2;" : "=f"(x), "=f"(y) : "l"(v));
}
__device__ __forceinline__ void fma2(ull &d, ull a, ull b) {
    asm("fma.rn.f32x2 %0, %1, %2, %0;" : "+l"(d) : "l"(a), "l"(b));
}

// ---------------- kernel 1: dense GEMV-8 + sigmoid, smem-staged sdr ----------------
__global__ __launch_bounds__(256, 2) void gemv_dense_kernel(
        const float* __restrict__ syn, const float* __restrict__ sdr) {
    extern __shared__ __align__(16) ull s_sdr[];   // [4][CHUNK]
    int tid  = threadIdx.x;
    int warp = blockIdx.x * 8 + (tid >> 5);        // 2048 warps
    int lane = tid & 31;
    int j0 = warp * 4;

    const float4* r0 = (const float4*)(syn + (size_t)(j0 + 0) * DIM);
    const float4* r1 = (const float4*)(syn + (size_t)(j0 + 1) * DIM);
    const float4* r2 = (const float4*)(syn + (size_t)(j0 + 2) * DIM);
    const float4* r3 = (const float4*)(syn + (size_t)(j0 + 3) * DIM);

    ull acc[4][4];
#pragma unroll
    for (int i = 0; i < 4; i++)
#pragma unroll
        for (int p = 0; p < 4; p++) acc[i][p] = 0ull;

    for (int c = 0; c < NCHUNK; c++) {
        int g4 = c * CHUNK / 4;

        __syncthreads();
        for (int t4 = tid; t4 < CHUNK / 4; t4 += 256) {
#pragma unroll
            for (int p = 0; p < 4; p++) {
                float4 lo = ((const float4*)(sdr + (size_t)(2 * p)     * DIM))[g4 + t4];
                float4 hi = ((const float4*)(sdr + (size_t)(2 * p + 1) * DIM))[g4 + t4];
                ull* d = &s_sdr[p * CHUNK + t4 * 4];
                d[0] = pack2(lo.x, hi.x);
                d[1] = pack2(lo.y, hi.y);
                d[2] = pack2(lo.z, hi.z);
                d[3] = pack2(lo.w, hi.w);
            }
        }
        __syncthreads();

        for (int t = 0; t < CHUNK / 4; t += 128) {
            float4 a0[4], a1[4], a2[4], a3[4];
#pragma unroll
            for (int u = 0; u < 4; u++) {
                int k4 = g4 + t + u * 32 + lane;
                a0[u] = r0[k4]; a1[u] = r1[k4]; a2[u] = r2[k4]; a3[u] = r3[k4];
            }
#pragma unroll
            for (int u = 0; u < 4; u++) {
                int kk = (t + u * 32 + lane) * 4;
                ulonglong2 sA[4], sB[4];
#pragma unroll
                for (int p = 0; p < 4; p++) {
                    const ulonglong2* sp = (const ulonglong2*)&s_sdr[p * CHUNK + kk];
                    sA[p] = sp[0];
                    sB[p] = sp[1];
                }
#pragma unroll
                for (int i = 0; i < 4; i++) {
                    float4 a = (i == 0 ? a0[u] : i == 1 ? a1[u] : i == 2 ? a2[u] : a3[u]);
                    ull px = pack2(a.x, a.x), py = pack2(a.y, a.y);
                    ull pz = pack2(a.z, a.z), pw = pack2(a.w, a.w);
#pragma unroll
                    for (int p = 0; p < 4; p++) {
                        fma2(acc[i][p], px, sA[p].x);
                        fma2(acc[i][p], py, sA[p].y);
                        fma2(acc[i][p], pz, sB[p].x);
                        fma2(acc[i][p], pw, sB[p].y);
                    }
                }
            }
        }
    }

#pragma unroll
    for (int i = 0; i < 4; i++) {
#pragma unroll
        for (int p = 0; p < 4; p++) {
            float x, y;
            unpack2(acc[i][p], x, y);
#pragma unroll
            for (int o = 16; o > 0; o >>= 1) {
                x += __shfl_down_sync(0xFFFFFFFFu, x, o);
                y += __shfl_down_sync(0xFFFFFFFFu, y, o);
            }
            if (lane == 0) {
                g_act[(size_t)(2 * p)     * DIM + (j0 + i)] = sigmoidf(x);
                g_act[(size_t)(2 * p + 1) * DIM + (j0 + i)] = sigmoidf(y);
            }
        }
    }
}

// ---------------- kernel 2/4: per-row top-k via histogram select ----------------
// 1024 threads, 8 elements each. phase 0 -> compact sorted padded list;
// phase 1 -> final dense output row. Exact jax.lax.top_k tie semantics.
__global__ __launch_bounds__(TK_THREADS) void topk_kernel(float* __restrict__ full_out, int phase) {
    int b    = blockIdx.x;
    int tid  = threadIdx.x;
    int lane = tid & 31;
    int wid  = tid >> 5;
    const float* row = (phase == 0 ? g_act : g_z2) + (size_t)b * DIM;
    const float4* row4 = (const float4*)row;

    uint ub[8];
#pragma unroll
    for (int i = 0; i < 2; i++) {
        float4 v = row4[i * TK_THREADS + tid];
        ub[i * 4 + 0] = __float_as_uint(v.x);
        ub[i * 4 + 1] = __float_as_uint(v.y);
        ub[i * 4 + 2] = __float_as_uint(v.z);
        ub[i * 4 + 3] = __float_as_uint(v.w);
    }

    __shared__ uint  s_h[NBINS];
    __shared__ int   s_wsum[32], s_wsuf[32];
    __shared__ int   s_B, s_cntgt, s_nc, s_c05;
    __shared__ uint  s_Tsh;
    __shared__ int   s_nselsh;
    __shared__ uint  s_cb[CCAP];
    __shared__ int   s_cp[CCAP];
    __shared__ int   s_tie[64];
    __shared__ float s_outv[64];
    __shared__ int   s_outi[64];
    __shared__ int   s_cnt[40];
    __shared__ int   s_ntie, s_slot;

#pragma unroll
    for (int q = 0; q < NBINS / TK_THREADS; q++) s_h[q * TK_THREADS + tid] = 0u;
    if (tid < 40) s_cnt[tid] = 0;
    if (tid == 0) { s_nc = 0; s_c05 = 0; s_ntie = 0; s_slot = 0; }

    if (phase == 1) {                // zero output row (ordered by later barriers)
        float4* o4 = (float4*)(full_out + (size_t)b * DIM);
        float4 z = make_float4(0.f, 0.f, 0.f, 0.f);
#pragma unroll
        for (int i = 0; i < 2; i++) o4[i * TK_THREADS + tid] = z;
    }
    __syncthreads();

    // count >= 0.5 and histogram the upper half
    {
        int c = 0;
#pragma unroll
        for (int i = 0; i < 8; i++) c += (ub[i] >= 0x3F000000u);
#pragma unroll
        for (int o = 16; o > 0; o >>= 1) c += __shfl_xor_sync(0xFFFFFFFFu, c, o);
        if (lane == 0) atomicAdd(&s_c05, c);
#pragma unroll
        for (int i = 0; i < 8; i++) {
            if (ub[i] >= 0x3F000000u) {
                uint bin = min((uint)(NBINS - 1), (ub[i] - 0x3F000000u) >> 12);
                atomicAdd(&s_h[bin], 1u);
            }
        }
    }
    __syncthreads();

    uint T = 0;
    int  nsel = 0;
    bool primary = (s_c05 >= TOPK);

    if (primary) {
        // suffix scan over 2048 bins (2 per thread)
        uint h0 = s_h[tid * 2 + 0], h1 = s_h[tid * 2 + 1];
        int local = (int)(h0 + h1);
        int x = local;
#pragma unroll
        for (int o = 1; o < 32; o <<= 1) {
            int v = __shfl_down_sync(0xFFFFFFFFu, x, o);
            if (lane + o < 32) x += v;
        }
        if (lane == 0) s_wsum[wid] = x;        // warp total
        __syncthreads();
        if (wid == 0) {
            int w = s_wsum[lane];
#pragma unroll
            for (int o = 1; o < 32; o <<= 1) {
                int v = __shfl_down_sync(0xFFFFFFFFu, w, o);
                if (lane + o < 32) w += v;
            }
            s_wsuf[lane] = w;                  // suffix over warps >= lane
        }
        __syncthreads();
        int incl = x + ((wid < 31) ? s_wsuf[wid + 1] : 0);
        int excl = incl - local;
        int c1 = excl + (int)h1;
        int c0 = c1 + (int)h0;
        if (c0 >= TOPK && c1 < TOPK)  { s_B = tid * 2 + 0; s_cntgt = c1; }
        if (c1 >= TOPK && excl < TOPK){ s_B = tid * 2 + 1; s_cntgt = excl; }
        __syncthreads();
        int B = s_B, cnt_gt = s_cntgt;

        // gather candidates in bin B
#pragma unroll
        for (int i = 0; i < 8; i++) {
            if (ub[i] >= 0x3F000000u) {
                uint bin = min((uint)(NBINS - 1), (ub[i] - 0x3F000000u) >> 12);
                if ((int)bin == B) {
                    int t = atomicAdd(&s_nc, 1);
                    if (t < CCAP) {
                        s_cb[t] = ub[i];
                        s_cp[t] = (i >> 2) * 4096 + tid * 4 + (i & 3);
                    }
                }
            }
        }
        __syncthreads();
        int nc = s_nc;
        if (nc <= CCAP) {
            if (tid == 0) {
                for (int q = 1; q < nc; q++) {       // bits desc, pos asc on ties
                    uint vb = s_cb[q]; int vp = s_cp[q];
                    int y = q - 1;
                    while (y >= 0 && (s_cb[y] < vb || (s_cb[y] == vb && s_cp[y] > vp))) {
                        s_cb[y + 1] = s_cb[y]; s_cp[y + 1] = s_cp[y]; y--;
                    }
                    s_cb[y + 1] = vb; s_cp[y + 1] = vp;
                }
                int need = TOPK - cnt_gt;
                uint Tv = s_cb[need - 1];
                int first = 0;
                while (s_cb[first] != Tv) first++;
                int ns = need - first;
                if (ns > 64) ns = 64;
                for (int q = 0; q < ns; q++) s_tie[q] = s_cp[first + q];
                s_Tsh = Tv;
                s_nselsh = ns;
            }
            __syncthreads();
            T = s_Tsh;
            nsel = s_nselsh;
        } else {
            primary = false;
        }
    }

    if (!primary) {
        // fallback: binary search over float bits + tie machinery
        uint lo = 0u, hi = 0x3F800001u;
        int it = 0;
        while (hi - lo > 1u) {
            uint mid = lo + ((hi - lo) >> 1);
            int c = 0;
#pragma unroll
            for (int i = 0; i < 8; i++) c += (ub[i] >= mid);
#pragma unroll
            for (int o = 16; o > 0; o >>= 1) c += __shfl_xor_sync(0xFFFFFFFFu, c, o);
            if (lane == 0) atomicAdd(&s_cnt[it], c);
            __syncthreads();
            int tot = s_cnt[it];
            it++;
            if (tot >= TOPK) lo = mid; else hi = mid;
        }
        T = lo;
        {
            int c = 0;
#pragma unroll
            for (int i = 0; i < 8; i++) c += (ub[i] > T);
#pragma unroll
            for (int o = 16; o > 0; o >>= 1) c += __shfl_xor_sync(0xFFFFFFFFu, c, o);
            if (lane == 0) atomicAdd(&s_cnt[33], c);
        }
#pragma unroll
        for (int i = 0; i < 8; i++) {
            if (ub[i] == T) {
                int pos = (i >> 2) * 4096 + tid * 4 + (i & 3);
                int t = atomicAdd(&s_ntie, 1);
                if (t < 64) s_tie[t] = pos;
            }
        }
        __syncthreads();
        int cnt_gt = s_cnt[33];
        int needed = TOPK - cnt_gt;
        int ntie = min(s_ntie, 64);
        if (tid == 0) {
            for (int q = 1; q < ntie; q++) {
                int v = s_tie[q], y = q - 1;
                while (y >= 0 && s_tie[y] > v) { s_tie[y + 1] = s_tie[y]; y--; }
                s_tie[y + 1] = v;
            }
        }
        __syncthreads();
        nsel = min(needed, 64);
    }

    // ---- selection pass (common) ----
    float* orow = full_out + (size_t)b * DIM;
#pragma unroll
    for (int i = 0; i < 8; i++) {
        uint u = ub[i];
        int pos = (i >> 2) * 4096 + tid * 4 + (i & 3);
        bool take = false;
        if (u > T) {
            take = true;
        } else if (u == T) {
            for (int q = 0; q < nsel; q++) take |= (s_tie[q] == pos);
        }
        if (take) {
            if (phase == 0) {
                int slot = atomicAdd(&s_slot, 1);
                s_outv[slot] = __uint_as_float(u);
                s_outi[slot] = pos;
            } else {
                orow[pos] = __uint_as_float(u);
            }
        }
    }

    if (phase == 0) {
        __syncthreads();
        if (tid < TOPK) {
            int my_i = s_outi[tid];
            float my_v = s_outv[tid];
            int rank = 0;
#pragma unroll 10
            for (int q = 0; q < TOPK; q++) rank += (s_outi[q] < my_i);
            g_vals[b * 64 + rank] = my_v;
            g_idxs[b * 64 + rank] = my_i;
        } else if (tid < 64) {                 // pad entries: val 0, col 0
            g_vals[b * 64 + tid] = 0.0f;
            g_idxs[b * 64 + tid] = 0;
        }
    }
}

// ---------------- kernel 3: sparse GEMV, per-batch sorted sweep ----------------
// Warp owns row j; for each batch b, lanes sweep its 64 (padded) column-
// ascending entries: entry t and t+32. Per thread: 16 independent LDGs +
// 16 FFMAs — no predicated accumulate, no merge.
__global__ __launch_bounds__(256) void gemv_sparse_kernel(const float* __restrict__ syn) {
    int tid  = threadIdx.x;
    int w    = tid >> 5;
    int lane = tid & 31;
    int j = blockIdx.x * 8 + w;

    __shared__ float sv[BATCH][64];
    __shared__ int   si[BATCH][64];
    for (int t = tid; t < BATCH * 64; t += 256) {
        sv[t >> 6][t & 63] = g_vals[t];
        si[t >> 6][t & 63] = g_idxs[t];
    }
    __syncthreads();

    const float* __restrict__ row = syn + (size_t)j * DIM;
    float acc[BATCH];
#pragma unroll
    for (int b = 0; b < BATCH; b++) {
        acc[b] = sv[b][lane]      * __ldg(&row[si[b][lane]])
               + sv[b][lane + 32] * __ldg(&row[si[b][lane + 32]]);
    }

#pragma unroll
    for (int o = 16; o > 0; o >>= 1) {
#pragma unroll
        for (int b = 0; b < BATCH; b++) {
            acc[b] += __shfl_down_sync(0xFFFFFFFFu, acc[b], o);
        }
    }
    float mine = 0.0f;
#pragma unroll
    for (int b = 0; b < BATCH; b++) {
        float r = __shfl_sync(0xFFFFFFFFu, acc[b], 0);
        if (lane == b) mine = r;
    }
    if (lane < BATCH) {
        g_z2[(size_t)lane * DIM + j] = sigmoidf(mine);
    }
}

// ---------------- launch ----------------
extern "C" void kernel_launch(void* const* d_in, const int* in_sizes, int n_in,
                              void* d_out, int out_size) {
    const float* sdr = (const float*)d_in[0];   // [8, 8192]
    const float* syn = (const float*)d_in[1];   // [8192, 8192]
    float* out = (float*)d_out;                 // [8, 8192]
    (void)in_sizes; (void)n_in; (void)out_size;

    static int smem_set = 0;
    if (!smem_set) {
        cudaFuncSetAttribute(gemv_dense_kernel,
                             cudaFuncAttributeMaxDynamicSharedMemorySize, DENSE_SMEM);
        smem_set = 1;
    }

    gemv_dense_kernel<<<DIM / 32, 256, DENSE_SMEM>>>(syn, sdr);  // 256 blocks
    topk_kernel<<<BATCH, TK_THREADS>>>(out, /*phase=*/0);  // -> sorted padded lists
    gemv_sparse_kernel<<<DIM / 8, 256>>>(syn);             // 1024 blocks, per-batch sweep
    topk_kernel<<<BATCH, TK_THREADS>>>(out, /*phase=*/1);  // -> dense output rows
}

// round 12
// speedup vs baseline: 1.2730x; 1.0006x over previous
#include <cuda_runtime.h>
#include <cstdint>
#include <math.h>

#define DIM   8192
#define BATCH 8
#define TOPK  60
#define CHUNK 2048             // dense-GEMV k-chunk staged in smem
#define NCHUNK (DIM / CHUNK)   // 4
#define DENSE_SMEM (4 * CHUNK * 8)   // 64 KB
#define NBINS 2048
#define CCAP  128              // candidate cap before fallback
#define TK_THREADS 1024

typedef unsigned long long ull;
typedef unsigned int uint;

// ---------------- device scratch (no allocations allowed) ----------------
__device__ float g_act[BATCH * DIM];               // step-1 sigmoid output
__device__ float g_z2 [BATCH * DIM];               // step-2 sigmoid output
__device__ float g_vals[BATCH * 64];               // top-k values, idx-sorted, 0-padded to 64
__device__ int   g_idxs[BATCH * 64];               // top-k indices, ascending, 0-padded

// ---------------- helpers ----------------
__device__ __forceinline__ float sigmoidf(float x) {
    return 1.0f / (1.0f + expf(-x));   // precise expf: selection must match reference
}
__device__ __forceinline__ ull pack2(float x, float y) {
    ull r; asm("mov.b64 %0, {%1,%2};" : "=l"(r) : "f"(x), "f"(y)); return r;
}
__device__ __forceinline__ void unpack2(ull v, float &x, float &y) {
    asm("mov.b64 {%0,%1}, %2;" : "=f"(x), "=f"(y) : "l"(v));
}
__device__ __forceinline__ void fma2(ull &d, ull a, ull b) {
    asm("fma.rn.f32x2 %0, %1, %2, %0;" : "+l"(d) : "l"(a), "l"(b));
}

// ---------------- kernel 1: dense GEMV-8 + sigmoid, smem-staged sdr ----------------
__global__ __launch_bounds__(256, 2) void gemv_dense_kernel(
        const float* __restrict__ syn, const float* __restrict__ sdr) {
    extern __shared__ __align__(16) ull s_sdr[];   // [4][CHUNK]
    int tid  = threadIdx.x;
    int warp = blockIdx.x * 8 + (tid >> 5);        // 2048 warps
    int lane = tid & 31;
    int j0 = warp * 4;

    const float4* r0 = (const float4*)(syn + (size_t)(j0 + 0) * DIM);
    const float4* r1 = (const float4*)(syn + (size_t)(j0 + 1) * DIM);
    const float4* r2 = (const float4*)(syn + (size_t)(j0 + 2) * DIM);
    const float4* r3 = (const float4*)(syn + (size_t)(j0 + 3) * DIM);

    ull acc[4][4];
#pragma unroll
    for (int i = 0; i < 4; i++)
#pragma unroll
        for (int p = 0; p < 4; p++) acc[i][p] = 0ull;

    for (int c = 0; c < NCHUNK; c++) {
        int g4 = c * CHUNK / 4;

        __syncthreads();
        for (int t4 = tid; t4 < CHUNK / 4; t4 += 256) {
#pragma unroll
            for (int p = 0; p < 4; p++) {
                float4 lo = ((const float4*)(sdr + (size_t)(2 * p)     * DIM))[g4 + t4];
                float4 hi = ((const float4*)(sdr + (size_t)(2 * p + 1) * DIM))[g4 + t4];
                ull* d = &s_sdr[p * CHUNK + t4 * 4];
                d[0] = pack2(lo.x, hi.x);
                d[1] = pack2(lo.y, hi.y);
                d[2] = pack2(lo.z, hi.z);
                d[3] = pack2(lo.w, hi.w);
            }
        }
        __syncthreads();

        for (int t = 0; t < CHUNK / 4; t += 128) {
            float4 a0[4], a1[4], a2[4], a3[4];
#pragma unroll
            for (int u = 0; u < 4; u++) {
                int k4 = g4 + t + u * 32 + lane;
                a0[u] = r0[k4]; a1[u] = r1[k4]; a2[u] = r2[k4]; a3[u] = r3[k4];
            }
#pragma unroll
            for (int u = 0; u < 4; u++) {
                int kk = (t + u * 32 + lane) * 4;
                ulonglong2 sA[4], sB[4];
#pragma unroll
                for (int p = 0; p < 4; p++) {
                    const ulonglong2* sp = (const ulonglong2*)&s_sdr[p * CHUNK + kk];
                    sA[p] = sp[0];
                    sB[p] = sp[1];
                }
#pragma unroll
                for (int i = 0; i < 4; i++) {
                    float4 a = (i == 0 ? a0[u] : i == 1 ? a1[u] : i == 2 ? a2[u] : a3[u]);
                    ull px = pack2(a.x, a.x), py = pack2(a.y, a.y);
                    ull pz = pack2(a.z, a.z), pw = pack2(a.w, a.w);
#pragma unroll
                    for (int p = 0; p < 4; p++) {
                        fma2(acc[i][p], px, sA[p].x);
                        fma2(acc[i][p], py, sA[p].y);
                        fma2(acc[i][p], pz, sB[p].x);
                        fma2(acc[i][p], pw, sB[p].y);
                    }
                }
            }
        }
    }

#pragma unroll
    for (int i = 0; i < 4; i++) {
#pragma unroll
        for (int p = 0; p < 4; p++) {
            float x, y;
            unpack2(acc[i][p], x, y);
#pragma unroll
            for (int o = 16; o > 0; o >>= 1) {
                x += __shfl_down_sync(0xFFFFFFFFu, x, o);
                y += __shfl_down_sync(0xFFFFFFFFu, y, o);
            }
            if (lane == 0) {
                g_act[(size_t)(2 * p)     * DIM + (j0 + i)] = sigmoidf(x);
                g_act[(size_t)(2 * p + 1) * DIM + (j0 + i)] = sigmoidf(y);
            }
        }
    }
}

// ---------------- kernel 2/4: per-row top-k via histogram select ----------------
// 1024 threads, 8 elements each. phase 0 -> compact sorted padded list;
// phase 1 -> final dense output row written in ONE coalesced full-row pass.
// Exact jax.lax.top_k tie semantics (lowest index wins at the cutoff).
__global__ __launch_bounds__(TK_THREADS) void topk_kernel(float* __restrict__ full_out, int phase) {
    int b    = blockIdx.x;
    int tid  = threadIdx.x;
    int lane = tid & 31;
    int wid  = tid >> 5;
    const float* row = (phase == 0 ? g_act : g_z2) + (size_t)b * DIM;
    const float4* row4 = (const float4*)row;

    uint ub[8];
#pragma unroll
    for (int i = 0; i < 2; i++) {
        float4 v = row4[i * TK_THREADS + tid];
        ub[i * 4 + 0] = __float_as_uint(v.x);
        ub[i * 4 + 1] = __float_as_uint(v.y);
        ub[i * 4 + 2] = __float_as_uint(v.z);
        ub[i * 4 + 3] = __float_as_uint(v.w);
    }

    __shared__ uint  s_h[NBINS];
    __shared__ int   s_wsum[32], s_wsuf[32];
    __shared__ int   s_B, s_cntgt, s_nc;
    __shared__ uint  s_Tsh;
    __shared__ int   s_nselsh;
    __shared__ uint  s_cb[CCAP];
    __shared__ int   s_cp[CCAP];
    __shared__ int   s_tie[64];
    __shared__ float s_outv[64];
    __shared__ int   s_outi[64];
    __shared__ int   s_cnt[40];
    __shared__ int   s_ntie, s_slot;

#pragma unroll
    for (int q = 0; q < NBINS / TK_THREADS; q++) s_h[q * TK_THREADS + tid] = 0u;
    if (tid < 40) s_cnt[tid] = 0;
    if (tid == 0) { s_nc = 0; s_ntie = 0; s_slot = 0; }
    __syncthreads();

    // histogram the upper half (values >= 0.5)
#pragma unroll
    for (int i = 0; i < 8; i++) {
        if (ub[i] >= 0x3F000000u) {
            uint bin = min((uint)(NBINS - 1), (ub[i] - 0x3F000000u) >> 12);
            atomicAdd(&s_h[bin], 1u);
        }
    }
    __syncthreads();

    // suffix scan over 2048 bins (2 per thread); total falls out of the scan
    uint h0 = s_h[tid * 2 + 0], h1 = s_h[tid * 2 + 1];
    int local = (int)(h0 + h1);
    int x = local;
#pragma unroll
    for (int o = 1; o < 32; o <<= 1) {
        int v = __shfl_down_sync(0xFFFFFFFFu, x, o);
        if (lane + o < 32) x += v;
    }
    if (lane == 0) s_wsum[wid] = x;        // warp total
    __syncthreads();
    if (wid == 0) {
        int w = s_wsum[lane];
#pragma unroll
        for (int o = 1; o < 32; o <<= 1) {
            int v = __shfl_down_sync(0xFFFFFFFFu, w, o);
            if (lane + o < 32) w += v;
        }
        s_wsuf[lane] = w;                  // suffix over warps >= lane
    }
    __syncthreads();

    uint T = 0;
    int  nsel = 0;
    bool primary = (s_wsuf[0] >= TOPK);    // total count of values >= 0.5

    if (primary) {
        int incl = x + ((wid < 31) ? s_wsuf[wid + 1] : 0);
        int excl = incl - local;
        int c1 = excl + (int)h1;
        int c0 = c1 + (int)h0;
        if (c0 >= TOPK && c1 < TOPK)  { s_B = tid * 2 + 0; s_cntgt = c1; }
        if (c1 >= TOPK && excl < TOPK){ s_B = tid * 2 + 1; s_cntgt = excl; }
        __syncthreads();
        int B = s_B, cnt_gt = s_cntgt;

        // gather candidates in bin B
#pragma unroll
        for (int i = 0; i < 8; i++) {
            if (ub[i] >= 0x3F000000u) {
                uint bin = min((uint)(NBINS - 1), (ub[i] - 0x3F000000u) >> 12);
                if ((int)bin == B) {
                    int t = atomicAdd(&s_nc, 1);
                    if (t < CCAP) {
                        s_cb[t] = ub[i];
                        s_cp[t] = (i >> 2) * 4096 + tid * 4 + (i & 3);
                    }
                }
            }
        }
        __syncthreads();
        int nc = s_nc;
        if (nc <= CCAP) {
            if (tid == 0) {
                for (int q = 1; q < nc; q++) {       // bits desc, pos asc on ties
                    uint vb = s_cb[q]; int vp = s_cp[q];
                    int y = q - 1;
                    while (y >= 0 && (s_cb[y] < vb || (s_cb[y] == vb && s_cp[y] > vp))) {
                        s_cb[y + 1] = s_cb[y]; s_cp[y + 1] = s_cp[y]; y--;
                    }
                    s_cb[y + 1] = vb; s_cp[y + 1] = vp;
                }
                int need = TOPK - cnt_gt;
                uint Tv = s_cb[need - 1];
                int first = 0;
                while (s_cb[first] != Tv) first++;
                int ns = need - first;
                if (ns > 64) ns = 64;
                for (int q = 0; q < ns; q++) s_tie[q] = s_cp[first + q];
                s_Tsh = Tv;
                s_nselsh = ns;
            }
            __syncthreads();
            T = s_Tsh;
            nsel = s_nselsh;
        } else {
            primary = false;
        }
    } else {
        __syncthreads();                   // match primary-path barrier structure
    }

    if (!primary) {
        // fallback: binary search over float bits + tie machinery
        uint lo = 0u, hi = 0x3F800001u;
        int it = 0;
        while (hi - lo > 1u) {
            uint mid = lo + ((hi - lo) >> 1);
            int c = 0;
#pragma unroll
            for (int i = 0; i < 8; i++) c += (ub[i] >= mid);
#pragma unroll
            for (int o = 16; o > 0; o >>= 1) c += __shfl_xor_sync(0xFFFFFFFFu, c, o);
            if (lane == 0) atomicAdd(&s_cnt[it], c);
            __syncthreads();
            int tot = s_cnt[it];
            it++;
            if (tot >= TOPK) lo = mid; else hi = mid;
        }
        T = lo;
        {
            int c = 0;
#pragma unroll
            for (int i = 0; i < 8; i++) c += (ub[i] > T);
#pragma unroll
            for (int o = 16; o > 0; o >>= 1) c += __shfl_xor_sync(0xFFFFFFFFu, c, o);
            if (lane == 0) atomicAdd(&s_cnt[33], c);
        }
#pragma unroll
        for (int i = 0; i < 8; i++) {
            if (ub[i] == T) {
                int pos = (i >> 2) * 4096 + tid * 4 + (i & 3);
                int t = atomicAdd(&s_ntie, 1);
                if (t < 64) s_tie[t] = pos;
            }
        }
        __syncthreads();
        int cnt_gt = s_cnt[33];
        int needed = TOPK - cnt_gt;
        int ntie = min(s_ntie, 64);
        if (tid == 0) {
            for (int q = 1; q < ntie; q++) {
                int v = s_tie[q], y = q - 1;
                while (y >= 0 && s_tie[y] > v) { s_tie[y + 1] = s_tie[y]; y--; }
                s_tie[y + 1] = v;
            }
        }
        __syncthreads();
        nsel = min(needed, 64);
    }

    // ---- selection pass ----
    if (phase == 1) {
        // full-row coalesced write: (take ? val : 0) for every element
        float out[8];
#pragma unroll
        for (int i = 0; i < 8; i++) {
            uint u = ub[i];
            int pos = (i >> 2) * 4096 + tid * 4 + (i & 3);
            bool take = (u > T);
            if (u == T) {
                for (int q = 0; q < nsel; q++) take |= (s_tie[q] == pos);
            }
            out[i] = take ? __uint_as_float(u) : 0.0f;
        }
        float4* o4 = (float4*)(full_out + (size_t)b * DIM);
        o4[tid]              = make_float4(out[0], out[1], out[2], out[3]);
        o4[TK_THREADS + tid] = make_float4(out[4], out[5], out[6], out[7]);
    } else {
#pragma unroll
        for (int i = 0; i < 8; i++) {
            uint u = ub[i];
            int pos = (i >> 2) * 4096 + tid * 4 + (i & 3);
            bool take = (u > T);
            if (u == T) {
                for (int q = 0; q < nsel; q++) take |= (s_tie[q] == pos);
            }
            if (take) {
                int slot = atomicAdd(&s_slot, 1);
                s_outv[slot] = __uint_as_float(u);
                s_outi[slot] = pos;
            }
        }
        __syncthreads();
        if (tid < TOPK) {
            int my_i = s_outi[tid];
            float my_v = s_outv[tid];
            int rank = 0;
#pragma unroll 10
            for (int q = 0; q < TOPK; q++) rank += (s_outi[q] < my_i);
            g_vals[b * 64 + rank] = my_v;
            g_idxs[b * 64 + rank] = my_i;
        } else if (tid < 64) {                 // pad entries: val 0, col 0
            g_vals[b * 64 + tid] = 0.0f;
            g_idxs[b * 64 + tid] = 0;
        }
    }
}

// ---------------- kernel 3: sparse GEMV, per-batch sorted sweep ----------------
__global__ __launch_bounds__(256) void gemv_sparse_kernel(const float* __restrict__ syn) {
    int tid  = threadIdx.x;
    int w    = tid >> 5;
    int lane = tid & 31;
    int j = blockIdx.x * 8 + w;

    __shared__ float sv[BATCH][64];
    __shared__ int   si[BATCH][64];
    for (int t = tid; t < BATCH * 64; t += 256) {
        sv[t >> 6][t & 63] = g_vals[t];
        si[t >> 6][t & 63] = g_idxs[t];
    }
    __syncthreads();

    const float* __restrict__ row = syn + (size_t)j * DIM;
    float acc[BATCH];
#pragma unroll
    for (int b = 0; b < BATCH; b++) {
        acc[b] = sv[b][lane]      * __ldg(&row[si[b][lane]])
               + sv[b][lane + 32] * __ldg(&row[si[b][lane + 32]]);
    }

#pragma unroll
    for (int o = 16; o > 0; o >>= 1) {
#pragma unroll
        for (int b = 0; b < BATCH; b++) {
            acc[b] += __shfl_down_sync(0xFFFFFFFFu, acc[b], o);
        }
    }
    float mine = 0.0f;
#pragma unroll
    for (int b = 0; b < BATCH; b++) {
        float r = __shfl_sync(0xFFFFFFFFu, acc[b], 0);
        if (lane == b) mine = r;
    }
    if (lane < BATCH) {
        g_z2[(size_t)lane * DIM + j] = sigmoidf(mine);
    }
}

// ---------------- launch ----------------
extern "C" void kernel_launch(void* const* d_in, const int* in_sizes, int n_in,
                              void* d_out, int out_size) {
    const float* sdr = (const float*)d_in[0];   // [8, 8192]
    const float* syn = (const float*)d_in[1];   // [8192, 8192]
    float* out = (float*)d_out;                 // [8, 8192]
    (void)in_sizes; (void)n_in; (void)out_size;

    static int smem_set = 0;
    if (!smem_set) {
        cudaFuncSetAttribute(gemv_dense_kernel,
                             cudaFuncAttributeMaxDynamicSharedMemorySize, DENSE_SMEM);
        smem_set = 1;
    }

    gemv_dense_kernel<<<DIM / 32, 256, DENSE_SMEM>>>(syn, sdr);  // 256 blocks
    topk_kernel<<<BATCH, TK_THREADS>>>(out, /*phase=*/0);  // -> sorted padded lists
    gemv_sparse_kernel<<<DIM / 8, 256>>>(syn);             // 1024 blocks, per-batch sweep
    topk_kernel<<<BATCH, TK_THREADS>>>(out, /*phase=*/1);  // -> coalesced final rows
}

// round 13
// speedup vs baseline: 1.2863x; 1.0105x over previous
#include <cuda_runtime.h>
#include <cstdint>
#include <math.h>

#define DIM   8192
#define BATCH 8
#define TOPK  60
#define CHUNK 2048             // dense-GEMV k-chunk staged in smem
#define NCHUNK (DIM / CHUNK)   // 4
#define DENSE_SMEM (4 * CHUNK * 8)   // 64 KB
#define NBINS 2048
#define CCAP  128              // candidate cap before fallback
#define TK_THREADS 1024

typedef unsigned long long ull;
typedef unsigned int uint;

// ---------------- device scratch (no allocations allowed) ----------------
__device__ float g_act[BATCH * DIM];               // step-1 sigmoid output
__device__ float g_z2 [BATCH * DIM];               // step-2 sigmoid output
__device__ float g_vals[BATCH * 64];               // top-k values, idx-sorted, 0-padded to 64
__device__ int   g_idxs[BATCH * 64];               // top-k indices, ascending, 0-padded

// ---------------- helpers ----------------
__device__ __forceinline__ float sigmoidf(float x) {
    return 1.0f / (1.0f + expf(-x));   // precise expf: selection must match reference
}
__device__ __forceinline__ ull pack2(float x, float y) {
    ull r; asm("mov.b64 %0, {%1,%2};" : "=l"(r) : "f"(x), "f"(y)); return r;
}
__device__ __forceinline__ void unpack2(ull v, float &x, float &y) {
    asm("mov.b64 {%0,%1}, %2;" : "=f"(x), "=f"(y) : "l"(v));
}
__device__ __forceinline__ void fma2(ull &d, ull a, ull b) {
    asm("fma.rn.f32x2 %0, %1, %2, %0;" : "+l"(d) : "l"(a), "l"(b));
}

// ---------------- kernel 1: dense GEMV-8 + sigmoid, smem-staged sdr ----------------
// No intra-graph producer: PDL-launched but no dependency sync needed.
__global__ __launch_bounds__(256, 2) void gemv_dense_kernel(
        const float* __restrict__ syn, const float* __restrict__ sdr) {
    extern __shared__ __align__(16) ull s_sdr[];   // [4][CHUNK]
    int tid  = threadIdx.x;
    int warp = blockIdx.x * 8 + (tid >> 5);        // 2048 warps
    int lane = tid & 31;
    int j0 = warp * 4;

    cudaTriggerProgrammaticLaunchCompletion();     // let topk0 spin up early

    const float4* r0 = (const float4*)(syn + (size_t)(j0 + 0) * DIM);
    const float4* r1 = (const float4*)(syn + (size_t)(j0 + 1) * DIM);
    const float4* r2 = (const float4*)(syn + (size_t)(j0 + 2) * DIM);
    const float4* r3 = (const float4*)(syn + (size_t)(j0 + 3) * DIM);

    ull acc[4][4];
#pragma unroll
    for (int i = 0; i < 4; i++)
#pragma unroll
        for (int p = 0; p < 4; p++) acc[i][p] = 0ull;

    for (int c = 0; c < NCHUNK; c++) {
        int g4 = c * CHUNK / 4;

        __syncthreads();
        for (int t4 = tid; t4 < CHUNK / 4; t4 += 256) {
#pragma unroll
            for (int p = 0; p < 4; p++) {
                float4 lo = ((const float4*)(sdr + (size_t)(2 * p)     * DIM))[g4 + t4];
                float4 hi = ((const float4*)(sdr + (size_t)(2 * p + 1) * DIM))[g4 + t4];
                ull* d = &s_sdr[p * CHUNK + t4 * 4];
                d[0] = pack2(lo.x, hi.x);
                d[1] = pack2(lo.y, hi.y);
                d[2] = pack2(lo.z, hi.z);
                d[3] = pack2(lo.w, hi.w);
            }
        }
        __syncthreads();

        for (int t = 0; t < CHUNK / 4; t += 128) {
            float4 a0[4], a1[4], a2[4], a3[4];
#pragma unroll
            for (int u = 0; u < 4; u++) {
                int k4 = g4 + t + u * 32 + lane;
                a0[u] = r0[k4]; a1[u] = r1[k4]; a2[u] = r2[k4]; a3[u] = r3[k4];
            }
#pragma unroll
            for (int u = 0; u < 4; u++) {
                int kk = (t + u * 32 + lane) * 4;
                ulonglong2 sA[4], sB[4];
#pragma unroll
                for (int p = 0; p < 4; p++) {
                    const ulonglong2* sp = (const ulonglong2*)&s_sdr[p * CHUNK + kk];
                    sA[p] = sp[0];
                    sB[p] = sp[1];
                }
#pragma unroll
                for (int i = 0; i < 4; i++) {
                    float4 a = (i == 0 ? a0[u] : i == 1 ? a1[u] : i == 2 ? a2[u] : a3[u]);
                    ull px = pack2(a.x, a.x), py = pack2(a.y, a.y);
                    ull pz = pack2(a.z, a.z), pw = pack2(a.w, a.w);
#pragma unroll
                    for (int p = 0; p < 4; p++) {
                        fma2(acc[i][p], px, sA[p].x);
                        fma2(acc[i][p], py, sA[p].y);
                        fma2(acc[i][p], pz, sB[p].x);
                        fma2(acc[i][p], pw, sB[p].y);
                    }
                }
            }
        }
    }

#pragma unroll
    for (int i = 0; i < 4; i++) {
#pragma unroll
        for (int p = 0; p < 4; p++) {
            float x, y;
            unpack2(acc[i][p], x, y);
#pragma unroll
            for (int o = 16; o > 0; o >>= 1) {
                x += __shfl_down_sync(0xFFFFFFFFu, x, o);
                y += __shfl_down_sync(0xFFFFFFFFu, y, o);
            }
            if (lane == 0) {
                g_act[(size_t)(2 * p)     * DIM + (j0 + i)] = sigmoidf(x);
                g_act[(size_t)(2 * p + 1) * DIM + (j0 + i)] = sigmoidf(y);
            }
        }
    }
}

// ---------------- kernel 2/4: per-row top-k via histogram select ----------------
// PDL consumer: smem init runs pre-sync; row loads wait for the producer.
__global__ __launch_bounds__(TK_THREADS) void topk_kernel(float* __restrict__ full_out, int phase) {
    int b    = blockIdx.x;
    int tid  = threadIdx.x;
    int lane = tid & 31;
    int wid  = tid >> 5;

    __shared__ uint  s_h[NBINS];
    __shared__ int   s_wsum[32], s_wsuf[32];
    __shared__ int   s_B, s_cntgt, s_nc;
    __shared__ uint  s_Tsh;
    __shared__ int   s_nselsh;
    __shared__ uint  s_cb[CCAP];
    __shared__ int   s_cp[CCAP];
    __shared__ int   s_tie[64];
    __shared__ float s_outv[64];
    __shared__ int   s_outi[64];
    __shared__ int   s_cnt[40];
    __shared__ int   s_ntie, s_slot;

    cudaTriggerProgrammaticLaunchCompletion();     // let the next kernel spin up

    // non-dependent prologue: zero smem
#pragma unroll
    for (int q = 0; q < NBINS / TK_THREADS; q++) s_h[q * TK_THREADS + tid] = 0u;
    if (tid < 40) s_cnt[tid] = 0;
    if (tid == 0) { s_nc = 0; s_ntie = 0; s_slot = 0; }

    cudaGridDependencySynchronize();               // producer results now visible

    const float* row = (phase == 0 ? g_act : g_z2) + (size_t)b * DIM;
    const float4* row4 = (const float4*)row;

    uint ub[8];
#pragma unroll
    for (int i = 0; i < 2; i++) {
        float4 v = row4[i * TK_THREADS + tid];
        ub[i * 4 + 0] = __float_as_uint(v.x);
        ub[i * 4 + 1] = __float_as_uint(v.y);
        ub[i * 4 + 2] = __float_as_uint(v.z);
        ub[i * 4 + 3] = __float_as_uint(v.w);
    }
    __syncthreads();

    // histogram the upper half (values >= 0.5)
#pragma unroll
    for (int i = 0; i < 8; i++) {
        if (ub[i] >= 0x3F000000u) {
            uint bin = min((uint)(NBINS - 1), (ub[i] - 0x3F000000u) >> 12);
            atomicAdd(&s_h[bin], 1u);
        }
    }
    __syncthreads();

    // suffix scan over 2048 bins (2 per thread); total falls out of the scan
    uint h0 = s_h[tid * 2 + 0], h1 = s_h[tid * 2 + 1];
    int local = (int)(h0 + h1);
    int x = local;
#pragma unroll
    for (int o = 1; o < 32; o <<= 1) {
        int v = __shfl_down_sync(0xFFFFFFFFu, x, o);
        if (lane + o < 32) x += v;
    }
    if (lane == 0) s_wsum[wid] = x;        // warp total
    __syncthreads();
    if (wid == 0) {
        int w = s_wsum[lane];
#pragma unroll
        for (int o = 1; o < 32; o <<= 1) {
            int v = __shfl_down_sync(0xFFFFFFFFu, w, o);
            if (lane + o < 32) w += v;
        }
        s_wsuf[lane] = w;                  // suffix over warps >= lane
    }
    __syncthreads();

    uint T = 0;
    int  nsel = 0;
    bool primary = (s_wsuf[0] >= TOPK);    // total count of values >= 0.5

    if (primary) {
        int incl = x + ((wid < 31) ? s_wsuf[wid + 1] : 0);
        int excl = incl - local;
        int c1 = excl + (int)h1;
        int c0 = c1 + (int)h0;
        if (c0 >= TOPK && c1 < TOPK)  { s_B = tid * 2 + 0; s_cntgt = c1; }
        if (c1 >= TOPK && excl < TOPK){ s_B = tid * 2 + 1; s_cntgt = excl; }
        __syncthreads();
        int B = s_B, cnt_gt = s_cntgt;

        // gather candidates in bin B
#pragma unroll
        for (int i = 0; i < 8; i++) {
            if (ub[i] >= 0x3F000000u) {
                uint bin = min((uint)(NBINS - 1), (ub[i] - 0x3F000000u) >> 12);
                if ((int)bin == B) {
                    int t = atomicAdd(&s_nc, 1);
                    if (t < CCAP) {
                        s_cb[t] = ub[i];
                        s_cp[t] = (i >> 2) * 4096 + tid * 4 + (i & 3);
                    }
                }
            }
        }
        __syncthreads();
        int nc = s_nc;
        if (nc <= CCAP) {
            if (tid == 0) {
                for (int q = 1; q < nc; q++) {       // bits desc, pos asc on ties
                    uint vb = s_cb[q]; int vp = s_cp[q];
                    int y = q - 1;
                    while (y >= 0 && (s_cb[y] < vb || (s_cb[y] == vb && s_cp[y] > vp))) {
                        s_cb[y + 1] = s_cb[y]; s_cp[y + 1] = s_cp[y]; y--;
                    }
                    s_cb[y + 1] = vb; s_cp[y + 1] = vp;
                }
                int need = TOPK - cnt_gt;
                uint Tv = s_cb[need - 1];
                int first = 0;
                while (s_cb[first] != Tv) first++;
                int ns = need - first;
                if (ns > 64) ns = 64;
                for (int q = 0; q < ns; q++) s_tie[q] = s_cp[first + q];
                s_Tsh = Tv;
                s_nselsh = ns;
            }
            __syncthreads();
            T = s_Tsh;
            nsel = s_nselsh;
        } else {
            primary = false;
        }
    } else {
        __syncthreads();                   // match primary-path barrier structure
    }

    if (!primary) {
        // fallback: binary search over float bits + tie machinery
        uint lo = 0u, hi = 0x3F800001u;
        int it = 0;
        while (hi - lo > 1u) {
            uint mid = lo + ((hi - lo) >> 1);
            int c = 0;
#pragma unroll
            for (int i = 0; i < 8; i++) c += (ub[i] >= mid);
#pragma unroll
            for (int o = 16; o > 0; o >>= 1) c += __shfl_xor_sync(0xFFFFFFFFu, c, o);
            if (lane == 0) atomicAdd(&s_cnt[it], c);
            __syncthreads();
            int tot = s_cnt[it];
            it++;
            if (tot >= TOPK) lo = mid; else hi = mid;
        }
        T = lo;
        {
            int c = 0;
#pragma unroll
            for (int i = 0; i < 8; i++) c += (ub[i] > T);
#pragma unroll
            for (int o = 16; o > 0; o >>= 1) c += __shfl_xor_sync(0xFFFFFFFFu, c, o);
            if (lane == 0) atomicAdd(&s_cnt[33], c);
        }
#pragma unroll
        for (int i = 0; i < 8; i++) {
            if (ub[i] == T) {
                int pos = (i >> 2) * 4096 + tid * 4 + (i & 3);
                int t = atomicAdd(&s_ntie, 1);
                if (t < 64) s_tie[t] = pos;
            }
        }
        __syncthreads();
        int cnt_gt = s_cnt[33];
        int needed = TOPK - cnt_gt;
        int ntie = min(s_ntie, 64);
        if (tid == 0) {
            for (int q = 1; q < ntie; q++) {
                int v = s_tie[q], y = q - 1;
                while (y >= 0 && s_tie[y] > v) { s_tie[y + 1] = s_tie[y]; y--; }
                s_tie[y + 1] = v;
            }
        }
        __syncthreads();
        nsel = min(needed, 64);
    }

    // ---- selection pass ----
    if (phase == 1) {
        // full-row coalesced write: (take ? val : 0) for every element
        float out[8];
#pragma unroll
        for (int i = 0; i < 8; i++) {
            uint u = ub[i];
            int pos = (i >> 2) * 4096 + tid * 4 + (i & 3);
            bool take = (u > T);
            if (u == T) {
                for (int q = 0; q < nsel; q++) take |= (s_tie[q] == pos);
            }
            out[i] = take ? __uint_as_float(u) : 0.0f;
        }
        float4* o4 = (float4*)(full_out + (size_t)b * DIM);
        o4[tid]              = make_float4(out[0], out[1], out[2], out[3]);
        o4[TK_THREADS + tid] = make_float4(out[4], out[5], out[6], out[7]);
    } else {
#pragma unroll
        for (int i = 0; i < 8; i++) {
            uint u = ub[i];
            int pos = (i >> 2) * 4096 + tid * 4 + (i & 3);
            bool take = (u > T);
            if (u == T) {
                for (int q = 0; q < nsel; q++) take |= (s_tie[q] == pos);
            }
            if (take) {
                int slot = atomicAdd(&s_slot, 1);
                s_outv[slot] = __uint_as_float(u);
                s_outi[slot] = pos;
            }
        }
        __syncthreads();
        if (tid < TOPK) {
            int my_i = s_outi[tid];
            float my_v = s_outv[tid];
            int rank = 0;
#pragma unroll 10
            for (int q = 0; q < TOPK; q++) rank += (s_outi[q] < my_i);
            g_vals[b * 64 + rank] = my_v;
            g_idxs[b * 64 + rank] = my_i;
        } else if (tid < 64) {                 // pad entries: val 0, col 0
            g_vals[b * 64 + tid] = 0.0f;
            g_idxs[b * 64 + tid] = 0;
        }
    }
}

// ---------------- kernel 3: sparse GEMV, per-batch sorted sweep ----------------
__global__ __launch_bounds__(256) void gemv_sparse_kernel(const float* __restrict__ syn) {
    int tid  = threadIdx.x;
    int w    = tid >> 5;
    int lane = tid & 31;
    int j = blockIdx.x * 8 + w;

    __shared__ float sv[BATCH][64];
    __shared__ int   si[BATCH][64];

    cudaTriggerProgrammaticLaunchCompletion();     // let topk1 spin up
    cudaGridDependencySynchronize();               // topk0 results visible

    for (int t = tid; t < BATCH * 64; t += 256) {
        sv[t >> 6][t & 63] = g_vals[t];
        si[t >> 6][t & 63] = g_idxs[t];
    }
    __syncthreads();

    const float* __restrict__ row = syn + (size_t)j * DIM;
    float acc[BATCH];
#pragma unroll
    for (int b = 0; b < BATCH; b++) {
        acc[b] = sv[b][lane]      * __ldg(&row[si[b][lane]])
               + sv[b][lane + 32] * __ldg(&row[si[b][lane + 32]]);
    }

#pragma unroll
    for (int o = 16; o > 0; o >>= 1) {
#pragma unroll
        for (int b = 0; b < BATCH; b++) {
            acc[b] += __shfl_down_sync(0xFFFFFFFFu, acc[b], o);
        }
    }
    float mine = 0.0f;
#pragma unroll
    for (int b = 0; b < BATCH; b++) {
        float r = __shfl_sync(0xFFFFFFFFu, acc[b], 0);
        if (lane == b) mine = r;
    }
    if (lane < BATCH) {
        g_z2[(size_t)lane * DIM + j] = sigmoidf(mine);
    }
}

// ---------------- launch ----------------
extern "C" void kernel_launch(void* const* d_in, const int* in_sizes, int n_in,
                              void* d_out, int out_size) {
    const float* sdr = (const float*)d_in[0];   // [8, 8192]
    const float* syn = (const float*)d_in[1];   // [8192, 8192]
    float* out = (float*)d_out;                 // [8, 8192]
    (void)in_sizes; (void)n_in; (void)out_size;

    static int smem_set = 0;
    if (!smem_set) {
        cudaFuncSetAttribute(gemv_dense_kernel,
                             cudaFuncAttributeMaxDynamicSharedMemorySize, DENSE_SMEM);
        smem_set = 1;
    }

    cudaLaunchAttribute pdl[1];
    pdl[0].id = cudaLaunchAttributeProgrammaticStreamSerialization;
    pdl[0].val.programmaticStreamSerializationAllowed = 1;

    {   // dense GEMV (no producer; PDL attr lets it pipeline across replays)
        cudaLaunchConfig_t cfg = {};
        cfg.gridDim = dim3(DIM / 32, 1, 1);
        cfg.blockDim = dim3(256, 1, 1);
        cfg.dynamicSmemBytes = DENSE_SMEM;
        cfg.attrs = pdl; cfg.numAttrs = 1;
        cudaLaunchKernelEx(&cfg, gemv_dense_kernel, syn, sdr);
    }
    {   // topk phase 0
        cudaLaunchConfig_t cfg = {};
        cfg.gridDim = dim3(BATCH, 1, 1);
        cfg.blockDim = dim3(TK_THREADS, 1, 1);
        cfg.attrs = pdl; cfg.numAttrs = 1;
        cudaLaunchKernelEx(&cfg, topk_kernel, out, 0);
    }
    {   // sparse GEMV
        cudaLaunchConfig_t cfg = {};
        cfg.gridDim = dim3(DIM / 8, 1, 1);
        cfg.blockDim = dim3(256, 1, 1);
        cfg.attrs = pdl; cfg.numAttrs = 1;
        cudaLaunchKernelEx(&cfg, gemv_sparse_kernel, syn);
    }
    {   // topk phase 1
        cudaLaunchConfig_t cfg = {};
        cfg.gridDim = dim3(BATCH, 1, 1);
        cfg.blockDim = dim3(TK_THREADS, 1, 1);
        cfg.attrs = pdl; cfg.numAttrs = 1;
        cudaLaunchKernelEx(&cfg, topk_kernel, out, 1);
    }
}